// round 14
// baseline (speedup 1.0000x reference)
#include <cuda_runtime.h>
#include <cuda_fp16.h>
#include <math.h>
#include <stdint.h>

// ---------------------------------------------------------------------------
// Problem constants
// ---------------------------------------------------------------------------
#define BB     8
#define HH     32
#define WW     32
#define NC     384
#define GROUPS 6
#define HEADS  12
#define HC     32
#define GC     64
#define NPIX   (HH*WW)          // 1024
#define MTOT   (BB*NPIX)        // 8192
#define NCH    12               // K chunks of 32

// ---------------------------------------------------------------------------
// Scratch (static device globals — no allocation allowed)
// ---------------------------------------------------------------------------
__device__ float g_q  [MTOT*NC];
__device__ float g_t  [MTOT*NC];
__device__ float g_xs [MTOT*NC];
__device__ float g_k  [MTOT*NC];
__device__ float g_v  [MTOT*NC];
__device__ float g_o  [MTOT*NC];

// ---------------------------------------------------------------------------
// mma.sync / packed-f32x2 / cp.async helpers (base sm_103 ISA)
// ---------------------------------------------------------------------------
__device__ __forceinline__ uint32_t f2tf32(float x) {
    uint32_t r;
    asm("cvt.rna.tf32.f32 %0, %1;" : "=r"(r) : "f"(x));
    return r;
}
__device__ __forceinline__ float ex2f(float x) {
    float r;
    asm("ex2.approx.f32 %0, %1;" : "=f"(r) : "f"(x));
    return r;
}
__device__ __forceinline__ uint32_t f16x2(float lo, float hi) {
    uint32_t r;
    asm("cvt.rn.f16x2.f32 %0, %1, %2;" : "=r"(r) : "f"(hi), "f"(lo));
    return r;
}
__device__ __forceinline__ uint16_t f16b(float x) {
    uint16_t r;
    asm("cvt.rn.f16.f32 %0, %1;" : "=h"(r) : "f"(x));
    return r;
}
__device__ __forceinline__ void mma_tf32(float* c, const uint32_t* a, const uint32_t* b) {
    asm volatile(
        "mma.sync.aligned.m16n8k8.row.col.f32.tf32.tf32.f32 "
        "{%0,%1,%2,%3}, {%4,%5,%6,%7}, {%8,%9}, {%0,%1,%2,%3};"
        : "+f"(c[0]), "+f"(c[1]), "+f"(c[2]), "+f"(c[3])
        : "r"(a[0]), "r"(a[1]), "r"(a[2]), "r"(a[3]), "r"(b[0]), "r"(b[1]));
}
__device__ __forceinline__ void mma_f16(float* c, const uint32_t* a, const uint32_t* b) {
    asm volatile(
        "mma.sync.aligned.m16n8k16.row.col.f32.f16.f16.f32 "
        "{%0,%1,%2,%3}, {%4,%5,%6,%7}, {%8,%9}, {%0,%1,%2,%3};"
        : "+f"(c[0]), "+f"(c[1]), "+f"(c[2]), "+f"(c[3])
        : "r"(a[0]), "r"(a[1]), "r"(a[2]), "r"(a[3]), "r"(b[0]), "r"(b[1]));
}
#define FMA2(d, a, b) \
    asm("fma.rn.f32x2 %0, %1, %2, %0;" : "+l"(d) : "l"(a), "l"(b))
__device__ __forceinline__ uint64_t packf2(float lo, float hi) {
    uint64_t r;
    asm("mov.b64 %0, {%1, %2};" : "=l"(r) : "f"(lo), "f"(hi));
    return r;
}
__device__ __forceinline__ float2 unpackf2(uint64_t v) {
    float2 r;
    asm("mov.b64 {%0, %1}, %2;" : "=f"(r.x), "=f"(r.y) : "l"(v));
    return r;
}
__device__ __forceinline__ void cp16(uint32_t saddr, const void* gptr) {
    asm volatile("cp.async.ca.shared.global [%0], [%1], 16;"
                 :: "r"(saddr), "l"(gptr));
}
#define CP_COMMIT() asm volatile("cp.async.commit_group;" ::: "memory")
#define CP_WAIT0()  asm volatile("cp.async.wait_group 0;"  ::: "memory")

// single dynamic-smem symbol for the whole TU
extern __shared__ uint32_t dynsm[];

// ---------------------------------------------------------------------------
// Pipelined tf32 mma GEMM (R11-proven): 256 thr, warp tile 32x64, cp.async
// double-buffered raw fp32 tiles, cvt at fragment load. Now with
// __launch_bounds__(256, 3): smem 71.7KB*3 = 215KB fits; regs forced <= 85.
// ---------------------------------------------------------------------------
#define GSA 36
#define GSB 136
#define GEMM_SMEM ((2*128*GSA + 2*32*GSB) * 4)

__device__ __forceinline__ void gemm_body_v3(
    const float* __restrict__ A, const float* __restrict__ W,
    const float* __restrict__ bias, float* __restrict__ C)
{
    float* As = reinterpret_cast<float*>(dynsm);
    float* Bs = As + 2 * 128 * GSA;
    const uint32_t sA = (uint32_t)__cvta_generic_to_shared(As);
    const uint32_t sB = (uint32_t)__cvta_generic_to_shared(Bs);

    const int tid = threadIdx.x, lane = tid & 31, wid = tid >> 5;
    const int wm = wid & 3, wn = wid >> 2;
    const int bm = blockIdx.x * 128, bn = blockIdx.y * 128;
    const int lq = lane >> 2, lr = lane & 3;

    float acc[2][8][4];
    #pragma unroll
    for (int i = 0; i < 2; i++)
        #pragma unroll
        for (int j = 0; j < 8; j++)
            #pragma unroll
            for (int t = 0; t < 4; t++) acc[i][j][t] = 0.f;

    auto stage = [&](int c, int buf) {
        #pragma unroll
        for (int l = 0; l < 4; l++) {
            int idx = tid + l * 256;
            int ra = idx >> 3, ca = idx & 7;
            cp16(sA + (buf * 128 * GSA + ra * GSA + ca * 4) * 4,
                 &A[(size_t)(bm + ra) * NC + c * 32 + ca * 4]);
            int rb = idx >> 5, cb = idx & 31;
            cp16(sB + (buf * 32 * GSB + rb * GSB + cb * 4) * 4,
                 &W[(size_t)(c * 32 + rb) * NC + bn + cb * 4]);
        }
        CP_COMMIT();
    };

    stage(0, 0);
    CP_WAIT0();
    __syncthreads();

    for (int c = 0; c < NCH; c++) {
        const int buf = c & 1;
        const bool more = (c + 1 < NCH);
        if (more) stage(c + 1, buf ^ 1);

        const float* Ab = As + buf * 128 * GSA;
        const float* Bb = Bs + buf * 32 * GSB;
        #pragma unroll
        for (int ks = 0; ks < 4; ks++) {
            const int k0 = ks * 8;
            uint32_t af[2][4];
            #pragma unroll
            for (int i = 0; i < 2; i++) {
                const int rb = wm * 32 + i * 16;
                af[i][0] = f2tf32(Ab[(rb +     lq) * GSA + k0 +     lr]);
                af[i][1] = f2tf32(Ab[(rb + 8 + lq) * GSA + k0 +     lr]);
                af[i][2] = f2tf32(Ab[(rb +     lq) * GSA + k0 + 4 + lr]);
                af[i][3] = f2tf32(Ab[(rb + 8 + lq) * GSA + k0 + 4 + lr]);
            }
            #pragma unroll
            for (int j = 0; j < 8; j++) {
                uint32_t bf[2];
                const int col = wn * 64 + j * 8 + lq;
                bf[0] = f2tf32(Bb[(k0 +     lr) * GSB + col]);
                bf[1] = f2tf32(Bb[(k0 + 4 + lr) * GSB + col]);
                mma_tf32(acc[0][j], af[0], bf);
                mma_tf32(acc[1][j], af[1], bf);
            }
        }
        if (more) CP_WAIT0();
        __syncthreads();
    }

    #pragma unroll
    for (int j = 0; j < 8; j++) {
        const int col = bn + wn * 64 + j * 8 + lr * 2;
        const float b0 = bias[col], b1 = bias[col + 1];
        #pragma unroll
        for (int i = 0; i < 2; i++) {
            const int r0 = bm + wm * 32 + i * 16 + lq;
            *reinterpret_cast<float2*>(&C[(size_t)r0 * NC + col]) =
                make_float2(acc[i][j][0] + b0, acc[i][j][1] + b1);
            *reinterpret_cast<float2*>(&C[(size_t)(r0 + 8) * NC + col]) =
                make_float2(acc[i][j][2] + b0, acc[i][j][3] + b1);
        }
    }
}

__global__ __launch_bounds__(256, 3) void gemm_mma_kernel(
    const float* __restrict__ A, const float* __restrict__ W,
    const float* __restrict__ bias, float* __restrict__ C)
{
    gemm_body_v3(A, W, bias, C);
}

__global__ __launch_bounds__(256, 3) void gemm_kv_kernel(
    const float* __restrict__ A,
    const float* __restrict__ Wk, const float* __restrict__ bk, float* __restrict__ K,
    const float* __restrict__ Wv, const float* __restrict__ bv, float* __restrict__ V)
{
    if (blockIdx.z == 0)
        gemm_body_v3(A, Wk, bk, K);
    else
        gemm_body_v3(A, Wv, bv, V);
}

// ---------------------------------------------------------------------------
// 3xTF32 compensated GEMM (near-fp32) — q projection only (proven).
// ---------------------------------------------------------------------------
#define G3_SMEM ((128*GSA*2 + 32*GSB*2) * 4)

__global__ __launch_bounds__(256) void gemm_mma3_kernel(
    const float* __restrict__ A, const float* __restrict__ W,
    const float* __restrict__ bias, float* __restrict__ C)
{
    uint32_t* s3 = dynsm;
    uint32_t* AsH = s3;
    uint32_t* AsL = s3 + 128 * GSA;
    uint32_t* BsH = s3 + 2 * 128 * GSA;
    uint32_t* BsL = BsH + 32 * GSB;

    const int tid = threadIdx.x, lane = tid & 31, wid = tid >> 5;
    const int wm = wid & 3, wn = wid >> 2;
    const int bm = blockIdx.x * 128, bn = blockIdx.y * 128;
    const int lq = lane >> 2, lr = lane & 3;

    float acc[2][8][4];
    #pragma unroll
    for (int i = 0; i < 2; i++)
        #pragma unroll
        for (int j = 0; j < 8; j++)
            #pragma unroll
            for (int t = 0; t < 4; t++) acc[i][j][t] = 0.f;

    for (int c = 0; c < NCH; c++) {
        #pragma unroll
        for (int l = 0; l < 4; l++) {
            int idx = tid + l * 256;
            int row = idx >> 3, c4 = idx & 7;
            float4 v = *reinterpret_cast<const float4*>(
                &A[(size_t)(bm + row) * NC + c * 32 + c4 * 4]);
            uint32_t* dh = &AsH[row * GSA + c4 * 4];
            uint32_t* dl = &AsL[row * GSA + c4 * 4];
            uint32_t h;
            h = f2tf32(v.x); dh[0] = h; dl[0] = f2tf32(v.x - __uint_as_float(h));
            h = f2tf32(v.y); dh[1] = h; dl[1] = f2tf32(v.y - __uint_as_float(h));
            h = f2tf32(v.z); dh[2] = h; dl[2] = f2tf32(v.z - __uint_as_float(h));
            h = f2tf32(v.w); dh[3] = h; dl[3] = f2tf32(v.w - __uint_as_float(h));
        }
        #pragma unroll
        for (int l = 0; l < 4; l++) {
            int idx = tid + l * 256;
            int row = idx >> 5, c4 = idx & 31;
            float4 v = *reinterpret_cast<const float4*>(
                &W[(size_t)(c * 32 + row) * NC + bn + c4 * 4]);
            uint32_t* dh = &BsH[row * GSB + c4 * 4];
            uint32_t* dl = &BsL[row * GSB + c4 * 4];
            uint32_t h;
            h = f2tf32(v.x); dh[0] = h; dl[0] = f2tf32(v.x - __uint_as_float(h));
            h = f2tf32(v.y); dh[1] = h; dl[1] = f2tf32(v.y - __uint_as_float(h));
            h = f2tf32(v.z); dh[2] = h; dl[2] = f2tf32(v.z - __uint_as_float(h));
            h = f2tf32(v.w); dh[3] = h; dl[3] = f2tf32(v.w - __uint_as_float(h));
        }
        __syncthreads();
        #pragma unroll
        for (int ks = 0; ks < 4; ks++) {
            const int k0 = ks * 8;
            uint32_t afh[2][4], afl[2][4];
            #pragma unroll
            for (int i = 0; i < 2; i++) {
                const int rb = wm * 32 + i * 16;
                afh[i][0] = AsH[(rb +     lq) * GSA + k0 +     lr];
                afh[i][1] = AsH[(rb + 8 + lq) * GSA + k0 +     lr];
                afh[i][2] = AsH[(rb +     lq) * GSA + k0 + 4 + lr];
                afh[i][3] = AsH[(rb + 8 + lq) * GSA + k0 + 4 + lr];
                afl[i][0] = AsL[(rb +     lq) * GSA + k0 +     lr];
                afl[i][1] = AsL[(rb + 8 + lq) * GSA + k0 +     lr];
                afl[i][2] = AsL[(rb +     lq) * GSA + k0 + 4 + lr];
                afl[i][3] = AsL[(rb + 8 + lq) * GSA + k0 + 4 + lr];
            }
            #pragma unroll
            for (int j = 0; j < 8; j++) {
                uint32_t bfh[2], bfl[2];
                const int col = wn * 64 + j * 8 + lq;
                bfh[0] = BsH[(k0 +     lr) * GSB + col];
                bfh[1] = BsH[(k0 + 4 + lr) * GSB + col];
                bfl[0] = BsL[(k0 +     lr) * GSB + col];
                bfl[1] = BsL[(k0 + 4 + lr) * GSB + col];
                #pragma unroll
                for (int i = 0; i < 2; i++) {
                    mma_tf32(acc[i][j], afl[i], bfh);
                    mma_tf32(acc[i][j], afh[i], bfl);
                    mma_tf32(acc[i][j], afh[i], bfh);
                }
            }
        }
        __syncthreads();
    }
    #pragma unroll
    for (int j = 0; j < 8; j++) {
        const int col = bn + wn * 64 + j * 8 + lr * 2;
        const float b0 = bias[col], b1 = bias[col + 1];
        #pragma unroll
        for (int i = 0; i < 2; i++) {
            const int r0 = bm + wm * 32 + i * 16 + lq;
            *reinterpret_cast<float2*>(&C[(size_t)r0 * NC + col]) =
                make_float2(acc[i][j][0] + b0, acc[i][j][1] + b1);
            *reinterpret_cast<float2*>(&C[(size_t)(r0 + 8) * NC + col]) =
                make_float2(acc[i][j][2] + b0, acc[i][j][3] + b1);
        }
    }
}

// ---------------------------------------------------------------------------
// Flash attention v4 (R11-proven): fp16 m16n8k16, fixed-max softmax,
// register-resident P, double-buffered fp16 K/V via register prefetch.
// ---------------------------------------------------------------------------
#define KW  20
#define VTW 36
#define ATTN_SMEM (2*64*KW*4 + 2*32*VTW*4)

__global__ __launch_bounds__(256) void attn_mma_kernel()
{
    uint32_t* Khw = dynsm;
    uint32_t* Vtw = dynsm + 2 * 64 * KW;

    const int tid = threadIdx.x, lane = tid & 31, wid = tid >> 5;
    const int lq = lane >> 2, lr = lane & 3;
    const int qt = blockIdx.x, h = blockIdx.y, b = blockIdx.z;
    const int q0 = qt * 128;

    const float qscale = 0.17677669529663689f * 1.4426950408889634f;
    uint32_t* Qw = dynsm;
    #pragma unroll
    for (int l = 0; l < 4; l++) {
        int idx = tid + l * 256;
        int row = idx >> 3, c4 = idx & 7;
        float4 v = *reinterpret_cast<const float4*>(
            &g_q[((size_t)b * NPIX + q0 + row) * NC + h * HC + c4 * 4]);
        Qw[row * KW + c4 * 2 + 0] = f16x2(v.x * qscale, v.y * qscale);
        Qw[row * KW + c4 * 2 + 1] = f16x2(v.z * qscale, v.w * qscale);
    }
    __syncthreads();
    uint32_t qf[2][4];
    {
        const int rb = wid * 16;
        #pragma unroll
        for (int ks = 0; ks < 2; ks++) {
            qf[ks][0] = Qw[(rb +     lq) * KW + lr +     8 * ks];
            qf[ks][1] = Qw[(rb + 8 + lq) * KW + lr +     8 * ks];
            qf[ks][2] = Qw[(rb +     lq) * KW + lr + 4 + 8 * ks];
            qf[ks][3] = Qw[(rb + 8 + lq) * KW + lr + 4 + 8 * ks];
        }
    }
    __syncthreads();

    float o[4][4];
    #pragma unroll
    for (int j = 0; j < 4; j++)
        #pragma unroll
        for (int t = 0; t < 4; t++) o[j][t] = 0.f;
    float l0 = 0.f, l1 = 0.f;

    auto ldtile = [&](int kt, float4* rk, float4* rv) {
        #pragma unroll
        for (int l = 0; l < 2; l++) {
            int idx = tid + l * 256;
            int key = idx >> 3, c4 = idx & 7;
            size_t base = ((size_t)b * NPIX + kt + key) * NC + h * HC + c4 * 4;
            rk[l] = *reinterpret_cast<const float4*>(&g_k[base]);
            rv[l] = *reinterpret_cast<const float4*>(&g_v[base]);
        }
    };
    auto sttile = [&](int buf, const float4* rk, const float4* rv) {
        uint32_t* K = Khw + buf * 64 * KW;
        uint16_t* Vt = reinterpret_cast<uint16_t*>(Vtw + buf * 32 * VTW);
        #pragma unroll
        for (int l = 0; l < 2; l++) {
            int idx = tid + l * 256;
            int key = idx >> 3, c4 = idx & 7;
            K[key * KW + c4 * 2 + 0] = f16x2(rk[l].x, rk[l].y);
            K[key * KW + c4 * 2 + 1] = f16x2(rk[l].z, rk[l].w);
            Vt[(c4 * 4 + 0) * (2 * VTW) + key] = f16b(rv[l].x);
            Vt[(c4 * 4 + 1) * (2 * VTW) + key] = f16b(rv[l].y);
            Vt[(c4 * 4 + 2) * (2 * VTW) + key] = f16b(rv[l].z);
            Vt[(c4 * 4 + 3) * (2 * VTW) + key] = f16b(rv[l].w);
        }
    };

    {
        float4 rk[2], rv[2];
        ldtile(0, rk, rv);
        sttile(0, rk, rv);
    }
    __syncthreads();

    for (int it = 0; it < 16; it++) {
        const int buf = it & 1;
        const bool more = (it < 15);
        float4 rk[2], rv[2];
        if (more) ldtile((it + 1) * 64, rk, rv);

        const uint32_t* K = Khw + buf * 64 * KW;
        const uint32_t* V = Vtw + buf * 32 * VTW;

        float s[8][4];
        #pragma unroll
        for (int j = 0; j < 8; j++)
            #pragma unroll
            for (int t = 0; t < 4; t++) s[j][t] = 0.f;
        #pragma unroll
        for (int ks = 0; ks < 2; ks++) {
            #pragma unroll
            for (int j = 0; j < 8; j++) {
                uint32_t bf[2];
                const int col = j * 8 + lq;
                bf[0] = K[col * KW + lr +     8 * ks];
                bf[1] = K[col * KW + lr + 4 + 8 * ks];
                mma_f16(s[j], qf[ks], bf);
            }
        }

        #pragma unroll
        for (int j = 0; j < 8; j++) {
            s[j][0] = ex2f(s[j][0]);
            s[j][1] = ex2f(s[j][1]);
            s[j][2] = ex2f(s[j][2]);
            s[j][3] = ex2f(s[j][3]);
            l0 += s[j][0] + s[j][1];
            l1 += s[j][2] + s[j][3];
        }

        if (more) sttile(buf ^ 1, rk, rv);

        #pragma unroll
        for (int ks = 0; ks < 4; ks++) {
            uint32_t ap[4];
            ap[0] = f16x2(s[2*ks    ][0], s[2*ks    ][1]);
            ap[1] = f16x2(s[2*ks    ][2], s[2*ks    ][3]);
            ap[2] = f16x2(s[2*ks + 1][0], s[2*ks + 1][1]);
            ap[3] = f16x2(s[2*ks + 1][2], s[2*ks + 1][3]);
            #pragma unroll
            for (int j = 0; j < 4; j++) {
                uint32_t bf[2];
                const int n = j * 8 + lq;
                bf[0] = V[n * VTW + lr +     8 * ks];
                bf[1] = V[n * VTW + lr + 4 + 8 * ks];
                mma_f16(o[j], ap, bf);
            }
        }
        __syncthreads();
    }

    l0 += __shfl_xor_sync(0xffffffffu, l0, 1);
    l0 += __shfl_xor_sync(0xffffffffu, l0, 2);
    l1 += __shfl_xor_sync(0xffffffffu, l1, 1);
    l1 += __shfl_xor_sync(0xffffffffu, l1, 2);
    const float il0 = 1.f / l0, il1 = 1.f / l1;
    const int rg = q0 + wid * 16 + lq;
    #pragma unroll
    for (int j = 0; j < 4; j++) {
        const int col = h * HC + j * 8 + lr * 2;
        *reinterpret_cast<float2*>(&g_o[((size_t)b * NPIX + rg) * NC + col]) =
            make_float2(o[j][0] * il0, o[j][1] * il0);
        *reinterpret_cast<float2*>(&g_o[((size_t)b * NPIX + rg + 8) * NC + col]) =
            make_float2(o[j][2] * il1, o[j][3] * il1);
    }
}

// ---------------------------------------------------------------------------
// Grouped 3x3 conv (packed fma.rn.f32x2, bit-exact fp32) — unchanged.
// ---------------------------------------------------------------------------
#define CONV_SMEM (64 * 6 * 36 * 4)

__global__ __launch_bounds__(256) void conv_off_kernel(
    const float* __restrict__ W, const float* __restrict__ bias)
{
    float* qs = reinterpret_cast<float*>(dynsm);
    const int bid = blockIdx.x;
    const int g  = bid % GROUPS;
    const int yt = (bid / GROUPS) & 7;
    const int b  = bid / (GROUPS * 8);
    const int y0 = yt * 4;
    const int tid = threadIdx.x;

    for (int i = tid; i < 64 * 6 * 34; i += 256) {
        int c  = i & 63;
        int xx = (i >> 6) % 34;
        int r  = i / (64 * 34);
        int yy = y0 + r - 1;
        float v = 0.f;
        if (xx >= 1 && xx <= 32 && yy >= 0 && yy < HH)
            v = g_q[((size_t)(b*HH + yy)*WW + (xx-1)) * NC + g*GC + c];
        qs[(c * 6 + r) * 36 + xx] = v;
    }
    __syncthreads();

    const int ty = tid >> 6;
    const int x0 = ((tid >> 4) & 3) * 8;
    const int oc = (tid & 15) * 4;
    const int y  = y0 + ty;

    uint64_t acc01[8], acc23[8];
    {
        float4 bv = *reinterpret_cast<const float4*>(&bias[g*GC + oc]);
        uint64_t b01 = packf2(bv.x, bv.y), b23 = packf2(bv.z, bv.w);
        #pragma unroll
        for (int xi = 0; xi < 8; xi++) { acc01[xi] = b01; acc23[xi] = b23; }
    }

    #pragma unroll
    for (int dy = 0; dy < 3; dy++) {
        const int r = ty + dy;
        #pragma unroll 2
        for (int ic = 0; ic < GC; ic++) {
            const float* qrow = &qs[(ic * 6 + r) * 36 + x0];
            uint64_t qp[10];
            #pragma unroll
            for (int j = 0; j < 10; j++) {
                float qv = qrow[j];
                qp[j] = packf2(qv, qv);
            }
            const uint64_t* wp0 = reinterpret_cast<const uint64_t*>(
                &W[(size_t)((dy*3 + 0) * GC + ic) * NC + g*GC + oc]);
            const uint64_t* wp1 = reinterpret_cast<const uint64_t*>(
                &W[(size_t)((dy*3 + 1) * GC + ic) * NC + g*GC + oc]);
            const uint64_t* wp2 = reinterpret_cast<const uint64_t*>(
                &W[(size_t)((dy*3 + 2) * GC + ic) * NC + g*GC + oc]);
            const uint64_t w0a = wp0[0], w0b = wp0[1];
            const uint64_t w1a = wp1[0], w1b = wp1[1];
            const uint64_t w2a = wp2[0], w2b = wp2[1];
            #pragma unroll
            for (int xi = 0; xi < 8; xi++) {
                FMA2(acc01[xi], w0a, qp[xi]);
                FMA2(acc23[xi], w0b, qp[xi]);
                FMA2(acc01[xi], w1a, qp[xi + 1]);
                FMA2(acc23[xi], w1b, qp[xi + 1]);
                FMA2(acc01[xi], w2a, qp[xi + 2]);
                FMA2(acc23[xi], w2b, qp[xi + 2]);
            }
        }
    }

    #pragma unroll
    for (int xi = 0; xi < 8; xi++) {
        float2 a = unpackf2(acc01[xi]);
        float2 c = unpackf2(acc23[xi]);
        float4 o = make_float4(a.x, a.y, c.x, c.y);
        *reinterpret_cast<float4*>(
            &g_t[((size_t)(b*HH + y)*WW + x0 + xi) * NC + g*GC + oc]) = o;
    }
}

// ---------------------------------------------------------------------------
// Fused: LayerNorm + erf-GELU + offset proj + tanh*range + ref grid + sample.
// ---------------------------------------------------------------------------
__global__ __launch_bounds__(384) void ln_sample_kernel(
    const float* __restrict__ ln_g, const float* __restrict__ ln_b,
    const float* __restrict__ wp, const float* __restrict__ x)
{
    const int p   = blockIdx.x;
    const int tid = threadIdx.x;
    const int wid  = tid >> 5;
    const int lane = tid & 31;

    float v = g_t[(size_t)p * NC + tid];

    __shared__ float red[2][12];
    __shared__ float sv[NC];
    __shared__ float spos[12];

    float s = v, sq = v * v;
    #pragma unroll
    for (int o = 16; o > 0; o >>= 1) {
        s  += __shfl_xor_sync(0xffffffffu, s,  o);
        sq += __shfl_xor_sync(0xffffffffu, sq, o);
    }
    if (lane == 0) { red[0][wid] = s; red[1][wid] = sq; }
    __syncthreads();
    if (tid < 32) {
        float a = (tid < 12) ? red[0][tid] : 0.f;
        float c = (tid < 12) ? red[1][tid] : 0.f;
        #pragma unroll
        for (int o = 8; o > 0; o >>= 1) {
            a += __shfl_xor_sync(0xffffffffu, a, o);
            c += __shfl_xor_sync(0xffffffffu, c, o);
        }
        if (tid == 0) { red[0][0] = a; red[1][0] = c; }
    }
    __syncthreads();
    const float mu  = red[0][0] * (1.f / NC);
    const float var = red[1][0] * (1.f / NC) - mu * mu;
    float nv = (v - mu) * rsqrtf(var + 1e-3f) * ln_g[tid] + ln_b[tid];
    nv = 0.5f * nv * (1.f + erff(nv * 0.70710678118654752f));

    sv[tid] = nv;
    __syncthreads();

    const int grp = wid >> 1, comp = wid & 1;
    float part = sv[grp*GC + lane]      * wp[lane * 2 + comp]
               + sv[grp*GC + 32 + lane] * wp[(32 + lane) * 2 + comp];
    #pragma unroll
    for (int o = 16; o > 0; o >>= 1)
        part += __shfl_xor_sync(0xffffffffu, part, o);

    const int pix = p & 1023;
    if (lane == 0) {
        const int yy = pix >> 5, xx = pix & 31;
        float refv = (comp == 0) ? (float)xx : (float)yy;
        spos[grp*2 + comp] = tanhf(part) * 16.f + refv;
    }
    __syncthreads();

    const int b = p >> 10;
    const int g = tid >> 6, c = tid & 63;
    const float p0 = spos[g*2 + 0];
    const float p1 = spos[g*2 + 1];
    const float xqf = p1 + 1.f;
    const float yqf = p0 + 1.f;
    const float x0f = fminf(fmaxf(floorf(xqf), 0.f), 32.f);
    const float y0f = fminf(fmaxf(floorf(yqf), 0.f), 32.f);
    const float ax = fminf(fmaxf(xqf - x0f, 0.f), 1.f);
    const float ay = fminf(fmaxf(yqf - y0f, 0.f), 1.f);
    const int x0 = (int)x0f, y0 = (int)y0f;

    const size_t choff = (size_t)g * GC + c;
    auto fetch = [&](int yy2, int xx2) -> float {
        if (yy2 < 1 || yy2 > 32 || xx2 < 1 || xx2 > 32) return 0.f;
        return x[((size_t)(b*HH + (yy2-1)) * WW + (xx2-1)) * NC + choff];
    };
    float tl = fetch(y0,     x0);
    float tr = fetch(y0,     x0 + 1);
    float bl = fetch(y0 + 1, x0);
    float br = fetch(y0 + 1, x0 + 1);
    float top = tl + ax * (tr - tl);
    float bot = bl + ax * (br - bl);
    g_xs[((size_t)b * NPIX + pix) * NC + choff] = top + ay * (bot - top);
}

// ---------------------------------------------------------------------------
// Launch
// ---------------------------------------------------------------------------
extern "C" void kernel_launch(void* const* d_in, const int* in_sizes, int n_in,
                              void* d_out, int out_size)
{
    const float* x      = (const float*)d_in[0];
    const float* w_q    = (const float*)d_in[1];
    const float* b_q    = (const float*)d_in[2];
    const float* w_off0 = (const float*)d_in[3];
    const float* b_off0 = (const float*)d_in[4];
    const float* ln_g   = (const float*)d_in[5];
    const float* ln_b   = (const float*)d_in[6];
    const float* w_offp = (const float*)d_in[7];
    const float* w_k    = (const float*)d_in[8];
    const float* b_k    = (const float*)d_in[9];
    const float* w_v    = (const float*)d_in[10];
    const float* b_v    = (const float*)d_in[11];
    const float* w_o    = (const float*)d_in[12];
    const float* b_o    = (const float*)d_in[13];
    float* out = (float*)d_out;

    float *pq, *pxs, *pk, *pv, *po;
    cudaGetSymbolAddress((void**)&pq,  g_q);
    cudaGetSymbolAddress((void**)&pxs, g_xs);
    cudaGetSymbolAddress((void**)&pk,  g_k);
    cudaGetSymbolAddress((void**)&pv,  g_v);
    cudaGetSymbolAddress((void**)&po,  g_o);

    cudaFuncSetAttribute(attn_mma_kernel,
                         cudaFuncAttributeMaxDynamicSharedMemorySize, ATTN_SMEM);
    cudaFuncSetAttribute(gemm_mma3_kernel,
                         cudaFuncAttributeMaxDynamicSharedMemorySize, G3_SMEM);
    cudaFuncSetAttribute(gemm_mma_kernel,
                         cudaFuncAttributeMaxDynamicSharedMemorySize, GEMM_SMEM);
    cudaFuncSetAttribute(gemm_kv_kernel,
                         cudaFuncAttributeMaxDynamicSharedMemorySize, GEMM_SMEM);
    cudaFuncSetAttribute(conv_off_kernel,
                         cudaFuncAttributeMaxDynamicSharedMemorySize, CONV_SMEM);

    dim3 ggrid(MTOT / 128, NC / 128);
    dim3 kvgrid(MTOT / 128, NC / 128, 2);
    dim3 agrid(NPIX / 128, HEADS, BB);

    // 1. q = x @ w_q + b_q   (3xTF32 compensated)
    gemm_mma3_kernel<<<ggrid, 256, G3_SMEM>>>(x, w_q, b_q, pq);
    // 2. grouped 3x3 conv on q -> g_t
    conv_off_kernel<<<BB * 8 * GROUPS, 256, CONV_SMEM>>>(w_off0, b_off0);
    // 3. LN + GELU + offset proj + tanh + ref + bilinear sample -> g_xs
    ln_sample_kernel<<<MTOT, NC>>>(ln_g, ln_b, w_offp, x);
    // 4. fused k+v projections (tf32 cp.async, 3 CTAs/SM)
    gemm_kv_kernel<<<kvgrid, 256, GEMM_SMEM>>>(pxs, w_k, b_k, pk, w_v, b_v, pv);
    // 5. attention (fp16 m16n8k16 flash, register-resident P) -> g_o
    attn_mma_kernel<<<agrid, 256, ATTN_SMEM>>>();
    // 6. y = o @ w_o + b_o -> d_out (tf32 cp.async, 3 CTAs/SM)
    gemm_mma_kernel<<<ggrid, 256, GEMM_SMEM>>>(po, w_o, b_o, out);
}

// round 15
// speedup vs baseline: 1.0691x; 1.0691x over previous
#include <cuda_runtime.h>
#include <cuda_fp16.h>
#include <math.h>
#include <stdint.h>

// ---------------------------------------------------------------------------
// Problem constants
// ---------------------------------------------------------------------------
#define BB     8
#define HH     32
#define WW     32
#define NC     384
#define GROUPS 6
#define HEADS  12
#define HC     32
#define GC     64
#define NPIX   (HH*WW)          // 1024
#define MTOT   (BB*NPIX)        // 8192
#define NCH    12               // K chunks of 32

// ---------------------------------------------------------------------------
// Scratch (static device globals — no allocation allowed)
// ---------------------------------------------------------------------------
__device__ float g_q  [MTOT*NC];
__device__ float g_t  [MTOT*NC];
__device__ float g_xs [MTOT*NC];
__device__ float g_k  [MTOT*NC];
__device__ float g_v  [MTOT*NC];
__device__ float g_o  [MTOT*NC];

// ---------------------------------------------------------------------------
// mma.sync / packed-f32x2 / cp.async helpers (base sm_103 ISA)
// ---------------------------------------------------------------------------
__device__ __forceinline__ uint32_t f2tf32(float x) {
    uint32_t r;
    asm("cvt.rna.tf32.f32 %0, %1;" : "=r"(r) : "f"(x));
    return r;
}
__device__ __forceinline__ float ex2f(float x) {
    float r;
    asm("ex2.approx.f32 %0, %1;" : "=f"(r) : "f"(x));
    return r;
}
__device__ __forceinline__ uint32_t f16x2(float lo, float hi) {
    uint32_t r;
    asm("cvt.rn.f16x2.f32 %0, %1, %2;" : "=r"(r) : "f"(hi), "f"(lo));
    return r;
}
__device__ __forceinline__ uint16_t f16b(float x) {
    uint16_t r;
    asm("cvt.rn.f16.f32 %0, %1;" : "=h"(r) : "f"(x));
    return r;
}
__device__ __forceinline__ void mma_tf32(float* c, const uint32_t* a, const uint32_t* b) {
    asm volatile(
        "mma.sync.aligned.m16n8k8.row.col.f32.tf32.tf32.f32 "
        "{%0,%1,%2,%3}, {%4,%5,%6,%7}, {%8,%9}, {%0,%1,%2,%3};"
        : "+f"(c[0]), "+f"(c[1]), "+f"(c[2]), "+f"(c[3])
        : "r"(a[0]), "r"(a[1]), "r"(a[2]), "r"(a[3]), "r"(b[0]), "r"(b[1]));
}
__device__ __forceinline__ void mma_f16(float* c, const uint32_t* a, const uint32_t* b) {
    asm volatile(
        "mma.sync.aligned.m16n8k16.row.col.f32.f16.f16.f32 "
        "{%0,%1,%2,%3}, {%4,%5,%6,%7}, {%8,%9}, {%0,%1,%2,%3};"
        : "+f"(c[0]), "+f"(c[1]), "+f"(c[2]), "+f"(c[3])
        : "r"(a[0]), "r"(a[1]), "r"(a[2]), "r"(a[3]), "r"(b[0]), "r"(b[1]));
}
#define FMA2(d, a, b) \
    asm("fma.rn.f32x2 %0, %1, %2, %0;" : "+l"(d) : "l"(a), "l"(b))
__device__ __forceinline__ uint64_t packf2(float lo, float hi) {
    uint64_t r;
    asm("mov.b64 %0, {%1, %2};" : "=l"(r) : "f"(lo), "f"(hi));
    return r;
}
__device__ __forceinline__ float2 unpackf2(uint64_t v) {
    float2 r;
    asm("mov.b64 {%0, %1}, %2;" : "=f"(r.x), "=f"(r.y) : "l"(v));
    return r;
}
__device__ __forceinline__ void cp16(uint32_t saddr, const void* gptr) {
    asm volatile("cp.async.ca.shared.global [%0], [%1], 16;"
                 :: "r"(saddr), "l"(gptr));
}
#define CP_COMMIT() asm volatile("cp.async.commit_group;" ::: "memory")
#define CP_WAIT0()  asm volatile("cp.async.wait_group 0;"  ::: "memory")

// single dynamic-smem symbol for the whole TU
extern __shared__ uint32_t dynsm[];

// ---------------------------------------------------------------------------
// Pipelined tf32 mma GEMM (R11-proven, NO launch_bounds minimum): 256 thr,
// warp tile 32x64, cp.async double-buffered raw fp32 tiles, cvt at frag load.
// ---------------------------------------------------------------------------
#define GSA 36
#define GSB 136
#define GEMM_SMEM ((2*128*GSA + 2*32*GSB) * 4)

__device__ __forceinline__ void gemm_body_v3(
    const float* __restrict__ A, const float* __restrict__ W,
    const float* __restrict__ bias, float* __restrict__ C)
{
    float* As = reinterpret_cast<float*>(dynsm);
    float* Bs = As + 2 * 128 * GSA;
    const uint32_t sA = (uint32_t)__cvta_generic_to_shared(As);
    const uint32_t sB = (uint32_t)__cvta_generic_to_shared(Bs);

    const int tid = threadIdx.x, lane = tid & 31, wid = tid >> 5;
    const int wm = wid & 3, wn = wid >> 2;
    const int bm = blockIdx.x * 128, bn = blockIdx.y * 128;
    const int lq = lane >> 2, lr = lane & 3;

    float acc[2][8][4];
    #pragma unroll
    for (int i = 0; i < 2; i++)
        #pragma unroll
        for (int j = 0; j < 8; j++)
            #pragma unroll
            for (int t = 0; t < 4; t++) acc[i][j][t] = 0.f;

    auto stage = [&](int c, int buf) {
        #pragma unroll
        for (int l = 0; l < 4; l++) {
            int idx = tid + l * 256;
            int ra = idx >> 3, ca = idx & 7;
            cp16(sA + (buf * 128 * GSA + ra * GSA + ca * 4) * 4,
                 &A[(size_t)(bm + ra) * NC + c * 32 + ca * 4]);
            int rb = idx >> 5, cb = idx & 31;
            cp16(sB + (buf * 32 * GSB + rb * GSB + cb * 4) * 4,
                 &W[(size_t)(c * 32 + rb) * NC + bn + cb * 4]);
        }
        CP_COMMIT();
    };

    stage(0, 0);
    CP_WAIT0();
    __syncthreads();

    for (int c = 0; c < NCH; c++) {
        const int buf = c & 1;
        const bool more = (c + 1 < NCH);
        if (more) stage(c + 1, buf ^ 1);

        const float* Ab = As + buf * 128 * GSA;
        const float* Bb = Bs + buf * 32 * GSB;
        #pragma unroll
        for (int ks = 0; ks < 4; ks++) {
            const int k0 = ks * 8;
            uint32_t af[2][4];
            #pragma unroll
            for (int i = 0; i < 2; i++) {
                const int rb = wm * 32 + i * 16;
                af[i][0] = f2tf32(Ab[(rb +     lq) * GSA + k0 +     lr]);
                af[i][1] = f2tf32(Ab[(rb + 8 + lq) * GSA + k0 +     lr]);
                af[i][2] = f2tf32(Ab[(rb +     lq) * GSA + k0 + 4 + lr]);
                af[i][3] = f2tf32(Ab[(rb + 8 + lq) * GSA + k0 + 4 + lr]);
            }
            #pragma unroll
            for (int j = 0; j < 8; j++) {
                uint32_t bf[2];
                const int col = wn * 64 + j * 8 + lq;
                bf[0] = f2tf32(Bb[(k0 +     lr) * GSB + col]);
                bf[1] = f2tf32(Bb[(k0 + 4 + lr) * GSB + col]);
                mma_tf32(acc[0][j], af[0], bf);
                mma_tf32(acc[1][j], af[1], bf);
            }
        }
        if (more) CP_WAIT0();
        __syncthreads();
    }

    #pragma unroll
    for (int j = 0; j < 8; j++) {
        const int col = bn + wn * 64 + j * 8 + lr * 2;
        const float b0 = bias[col], b1 = bias[col + 1];
        #pragma unroll
        for (int i = 0; i < 2; i++) {
            const int r0 = bm + wm * 32 + i * 16 + lq;
            *reinterpret_cast<float2*>(&C[(size_t)r0 * NC + col]) =
                make_float2(acc[i][j][0] + b0, acc[i][j][1] + b1);
            *reinterpret_cast<float2*>(&C[(size_t)(r0 + 8) * NC + col]) =
                make_float2(acc[i][j][2] + b0, acc[i][j][3] + b1);
        }
    }
}

__global__ __launch_bounds__(256) void gemm_mma_kernel(
    const float* __restrict__ A, const float* __restrict__ W,
    const float* __restrict__ bias, float* __restrict__ C)
{
    gemm_body_v3(A, W, bias, C);
}

__global__ __launch_bounds__(256) void gemm_kv_kernel(
    const float* __restrict__ A,
    const float* __restrict__ Wk, const float* __restrict__ bk, float* __restrict__ K,
    const float* __restrict__ Wv, const float* __restrict__ bv, float* __restrict__ V)
{
    if (blockIdx.z == 0)
        gemm_body_v3(A, Wk, bk, K);
    else
        gemm_body_v3(A, Wv, bv, V);
}

// ---------------------------------------------------------------------------
// 3xTF32 compensated GEMM v2 — q projection. cp.async double-buffered raw
// fp32 tiles; hi/lo tf32 split computed at fragment load (bit-identical to
// staging-time split). ONE sync per chunk, loads overlap 192-mma body.
// ---------------------------------------------------------------------------
__global__ __launch_bounds__(256) void gemm_mma3_kernel(
    const float* __restrict__ A, const float* __restrict__ W,
    const float* __restrict__ bias, float* __restrict__ C)
{
    float* As = reinterpret_cast<float*>(dynsm);
    float* Bs = As + 2 * 128 * GSA;
    const uint32_t sA = (uint32_t)__cvta_generic_to_shared(As);
    const uint32_t sB = (uint32_t)__cvta_generic_to_shared(Bs);

    const int tid = threadIdx.x, lane = tid & 31, wid = tid >> 5;
    const int wm = wid & 3, wn = wid >> 2;
    const int bm = blockIdx.x * 128, bn = blockIdx.y * 128;
    const int lq = lane >> 2, lr = lane & 3;

    float acc[2][8][4];
    #pragma unroll
    for (int i = 0; i < 2; i++)
        #pragma unroll
        for (int j = 0; j < 8; j++)
            #pragma unroll
            for (int t = 0; t < 4; t++) acc[i][j][t] = 0.f;

    auto stage = [&](int c, int buf) {
        #pragma unroll
        for (int l = 0; l < 4; l++) {
            int idx = tid + l * 256;
            int ra = idx >> 3, ca = idx & 7;
            cp16(sA + (buf * 128 * GSA + ra * GSA + ca * 4) * 4,
                 &A[(size_t)(bm + ra) * NC + c * 32 + ca * 4]);
            int rb = idx >> 5, cb = idx & 31;
            cp16(sB + (buf * 32 * GSB + rb * GSB + cb * 4) * 4,
                 &W[(size_t)(c * 32 + rb) * NC + bn + cb * 4]);
        }
        CP_COMMIT();
    };

    auto split = [](float v, uint32_t& h, uint32_t& l) {
        h = f2tf32(v);
        l = f2tf32(v - __uint_as_float(h));
    };

    stage(0, 0);
    CP_WAIT0();
    __syncthreads();

    for (int c = 0; c < NCH; c++) {
        const int buf = c & 1;
        const bool more = (c + 1 < NCH);
        if (more) stage(c + 1, buf ^ 1);

        const float* Ab = As + buf * 128 * GSA;
        const float* Bb = Bs + buf * 32 * GSB;
        #pragma unroll
        for (int ks = 0; ks < 4; ks++) {
            const int k0 = ks * 8;
            uint32_t afh[2][4], afl[2][4];
            #pragma unroll
            for (int i = 0; i < 2; i++) {
                const int rb = wm * 32 + i * 16;
                split(Ab[(rb +     lq) * GSA + k0 +     lr], afh[i][0], afl[i][0]);
                split(Ab[(rb + 8 + lq) * GSA + k0 +     lr], afh[i][1], afl[i][1]);
                split(Ab[(rb +     lq) * GSA + k0 + 4 + lr], afh[i][2], afl[i][2]);
                split(Ab[(rb + 8 + lq) * GSA + k0 + 4 + lr], afh[i][3], afl[i][3]);
            }
            #pragma unroll
            for (int j = 0; j < 8; j++) {
                uint32_t bfh[2], bfl[2];
                const int col = wn * 64 + j * 8 + lq;
                split(Bb[(k0 +     lr) * GSB + col], bfh[0], bfl[0]);
                split(Bb[(k0 + 4 + lr) * GSB + col], bfh[1], bfl[1]);
                #pragma unroll
                for (int i = 0; i < 2; i++) {
                    mma_tf32(acc[i][j], afl[i], bfh);
                    mma_tf32(acc[i][j], afh[i], bfl);
                    mma_tf32(acc[i][j], afh[i], bfh);
                }
            }
        }
        if (more) CP_WAIT0();
        __syncthreads();
    }
    #pragma unroll
    for (int j = 0; j < 8; j++) {
        const int col = bn + wn * 64 + j * 8 + lr * 2;
        const float b0 = bias[col], b1 = bias[col + 1];
        #pragma unroll
        for (int i = 0; i < 2; i++) {
            const int r0 = bm + wm * 32 + i * 16 + lq;
            *reinterpret_cast<float2*>(&C[(size_t)r0 * NC + col]) =
                make_float2(acc[i][j][0] + b0, acc[i][j][1] + b1);
            *reinterpret_cast<float2*>(&C[(size_t)(r0 + 8) * NC + col]) =
                make_float2(acc[i][j][2] + b0, acc[i][j][3] + b1);
        }
    }
}

// ---------------------------------------------------------------------------
// Flash attention v4 (R11-proven): fp16 m16n8k16, fixed-max softmax,
// register-resident P, double-buffered fp16 K/V via register prefetch.
// ---------------------------------------------------------------------------
#define KW  20
#define VTW 36
#define ATTN_SMEM (2*64*KW*4 + 2*32*VTW*4)

__global__ __launch_bounds__(256) void attn_mma_kernel()
{
    uint32_t* Khw = dynsm;
    uint32_t* Vtw = dynsm + 2 * 64 * KW;

    const int tid = threadIdx.x, lane = tid & 31, wid = tid >> 5;
    const int lq = lane >> 2, lr = lane & 3;
    const int qt = blockIdx.x, h = blockIdx.y, b = blockIdx.z;
    const int q0 = qt * 128;

    const float qscale = 0.17677669529663689f * 1.4426950408889634f;
    uint32_t* Qw = dynsm;
    #pragma unroll
    for (int l = 0; l < 4; l++) {
        int idx = tid + l * 256;
        int row = idx >> 3, c4 = idx & 7;
        float4 v = *reinterpret_cast<const float4*>(
            &g_q[((size_t)b * NPIX + q0 + row) * NC + h * HC + c4 * 4]);
        Qw[row * KW + c4 * 2 + 0] = f16x2(v.x * qscale, v.y * qscale);
        Qw[row * KW + c4 * 2 + 1] = f16x2(v.z * qscale, v.w * qscale);
    }
    __syncthreads();
    uint32_t qf[2][4];
    {
        const int rb = wid * 16;
        #pragma unroll
        for (int ks = 0; ks < 2; ks++) {
            qf[ks][0] = Qw[(rb +     lq) * KW + lr +     8 * ks];
            qf[ks][1] = Qw[(rb + 8 + lq) * KW + lr +     8 * ks];
            qf[ks][2] = Qw[(rb +     lq) * KW + lr + 4 + 8 * ks];
            qf[ks][3] = Qw[(rb + 8 + lq) * KW + lr + 4 + 8 * ks];
        }
    }
    __syncthreads();

    float o[4][4];
    #pragma unroll
    for (int j = 0; j < 4; j++)
        #pragma unroll
        for (int t = 0; t < 4; t++) o[j][t] = 0.f;
    float l0 = 0.f, l1 = 0.f;

    auto ldtile = [&](int kt, float4* rk, float4* rv) {
        #pragma unroll
        for (int l = 0; l < 2; l++) {
            int idx = tid + l * 256;
            int key = idx >> 3, c4 = idx & 7;
            size_t base = ((size_t)b * NPIX + kt + key) * NC + h * HC + c4 * 4;
            rk[l] = *reinterpret_cast<const float4*>(&g_k[base]);
            rv[l] = *reinterpret_cast<const float4*>(&g_v[base]);
        }
    };
    auto sttile = [&](int buf, const float4* rk, const float4* rv) {
        uint32_t* K = Khw + buf * 64 * KW;
        uint16_t* Vt = reinterpret_cast<uint16_t*>(Vtw + buf * 32 * VTW);
        #pragma unroll
        for (int l = 0; l < 2; l++) {
            int idx = tid + l * 256;
            int key = idx >> 3, c4 = idx & 7;
            K[key * KW + c4 * 2 + 0] = f16x2(rk[l].x, rk[l].y);
            K[key * KW + c4 * 2 + 1] = f16x2(rk[l].z, rk[l].w);
            Vt[(c4 * 4 + 0) * (2 * VTW) + key] = f16b(rv[l].x);
            Vt[(c4 * 4 + 1) * (2 * VTW) + key] = f16b(rv[l].y);
            Vt[(c4 * 4 + 2) * (2 * VTW) + key] = f16b(rv[l].z);
            Vt[(c4 * 4 + 3) * (2 * VTW) + key] = f16b(rv[l].w);
        }
    };

    {
        float4 rk[2], rv[2];
        ldtile(0, rk, rv);
        sttile(0, rk, rv);
    }
    __syncthreads();

    for (int it = 0; it < 16; it++) {
        const int buf = it & 1;
        const bool more = (it < 15);
        float4 rk[2], rv[2];
        if (more) ldtile((it + 1) * 64, rk, rv);

        const uint32_t* K = Khw + buf * 64 * KW;
        const uint32_t* V = Vtw + buf * 32 * VTW;

        float s[8][4];
        #pragma unroll
        for (int j = 0; j < 8; j++)
            #pragma unroll
            for (int t = 0; t < 4; t++) s[j][t] = 0.f;
        #pragma unroll
        for (int ks = 0; ks < 2; ks++) {
            #pragma unroll
            for (int j = 0; j < 8; j++) {
                uint32_t bf[2];
                const int col = j * 8 + lq;
                bf[0] = K[col * KW + lr +     8 * ks];
                bf[1] = K[col * KW + lr + 4 + 8 * ks];
                mma_f16(s[j], qf[ks], bf);
            }
        }

        #pragma unroll
        for (int j = 0; j < 8; j++) {
            s[j][0] = ex2f(s[j][0]);
            s[j][1] = ex2f(s[j][1]);
            s[j][2] = ex2f(s[j][2]);
            s[j][3] = ex2f(s[j][3]);
            l0 += s[j][0] + s[j][1];
            l1 += s[j][2] + s[j][3];
        }

        if (more) sttile(buf ^ 1, rk, rv);

        #pragma unroll
        for (int ks = 0; ks < 4; ks++) {
            uint32_t ap[4];
            ap[0] = f16x2(s[2*ks    ][0], s[2*ks    ][1]);
            ap[1] = f16x2(s[2*ks    ][2], s[2*ks    ][3]);
            ap[2] = f16x2(s[2*ks + 1][0], s[2*ks + 1][1]);
            ap[3] = f16x2(s[2*ks + 1][2], s[2*ks + 1][3]);
            #pragma unroll
            for (int j = 0; j < 4; j++) {
                uint32_t bf[2];
                const int n = j * 8 + lq;
                bf[0] = V[n * VTW + lr +     8 * ks];
                bf[1] = V[n * VTW + lr + 4 + 8 * ks];
                mma_f16(o[j], ap, bf);
            }
        }
        __syncthreads();
    }

    l0 += __shfl_xor_sync(0xffffffffu, l0, 1);
    l0 += __shfl_xor_sync(0xffffffffu, l0, 2);
    l1 += __shfl_xor_sync(0xffffffffu, l1, 1);
    l1 += __shfl_xor_sync(0xffffffffu, l1, 2);
    const float il0 = 1.f / l0, il1 = 1.f / l1;
    const int rg = q0 + wid * 16 + lq;
    #pragma unroll
    for (int j = 0; j < 4; j++) {
        const int col = h * HC + j * 8 + lr * 2;
        *reinterpret_cast<float2*>(&g_o[((size_t)b * NPIX + rg) * NC + col]) =
            make_float2(o[j][0] * il0, o[j][1] * il0);
        *reinterpret_cast<float2*>(&g_o[((size_t)b * NPIX + rg + 8) * NC + col]) =
            make_float2(o[j][2] * il1, o[j][3] * il1);
    }
}

// ---------------------------------------------------------------------------
// Grouped 3x3 conv (packed fma.rn.f32x2, bit-exact fp32) — unchanged.
// ---------------------------------------------------------------------------
#define CONV_SMEM (64 * 6 * 36 * 4)

__global__ __launch_bounds__(256) void conv_off_kernel(
    const float* __restrict__ W, const float* __restrict__ bias)
{
    float* qs = reinterpret_cast<float*>(dynsm);
    const int bid = blockIdx.x;
    const int g  = bid % GROUPS;
    const int yt = (bid / GROUPS) & 7;
    const int b  = bid / (GROUPS * 8);
    const int y0 = yt * 4;
    const int tid = threadIdx.x;

    for (int i = tid; i < 64 * 6 * 34; i += 256) {
        int c  = i & 63;
        int xx = (i >> 6) % 34;
        int r  = i / (64 * 34);
        int yy = y0 + r - 1;
        float v = 0.f;
        if (xx >= 1 && xx <= 32 && yy >= 0 && yy < HH)
            v = g_q[((size_t)(b*HH + yy)*WW + (xx-1)) * NC + g*GC + c];
        qs[(c * 6 + r) * 36 + xx] = v;
    }
    __syncthreads();

    const int ty = tid >> 6;
    const int x0 = ((tid >> 4) & 3) * 8;
    const int oc = (tid & 15) * 4;
    const int y  = y0 + ty;

    uint64_t acc01[8], acc23[8];
    {
        float4 bv = *reinterpret_cast<const float4*>(&bias[g*GC + oc]);
        uint64_t b01 = packf2(bv.x, bv.y), b23 = packf2(bv.z, bv.w);
        #pragma unroll
        for (int xi = 0; xi < 8; xi++) { acc01[xi] = b01; acc23[xi] = b23; }
    }

    #pragma unroll
    for (int dy = 0; dy < 3; dy++) {
        const int r = ty + dy;
        #pragma unroll 2
        for (int ic = 0; ic < GC; ic++) {
            const float* qrow = &qs[(ic * 6 + r) * 36 + x0];
            uint64_t qp[10];
            #pragma unroll
            for (int j = 0; j < 10; j++) {
                float qv = qrow[j];
                qp[j] = packf2(qv, qv);
            }
            const uint64_t* wp0 = reinterpret_cast<const uint64_t*>(
                &W[(size_t)((dy*3 + 0) * GC + ic) * NC + g*GC + oc]);
            const uint64_t* wp1 = reinterpret_cast<const uint64_t*>(
                &W[(size_t)((dy*3 + 1) * GC + ic) * NC + g*GC + oc]);
            const uint64_t* wp2 = reinterpret_cast<const uint64_t*>(
                &W[(size_t)((dy*3 + 2) * GC + ic) * NC + g*GC + oc]);
            const uint64_t w0a = wp0[0], w0b = wp0[1];
            const uint64_t w1a = wp1[0], w1b = wp1[1];
            const uint64_t w2a = wp2[0], w2b = wp2[1];
            #pragma unroll
            for (int xi = 0; xi < 8; xi++) {
                FMA2(acc01[xi], w0a, qp[xi]);
                FMA2(acc23[xi], w0b, qp[xi]);
                FMA2(acc01[xi], w1a, qp[xi + 1]);
                FMA2(acc23[xi], w1b, qp[xi + 1]);
                FMA2(acc01[xi], w2a, qp[xi + 2]);
                FMA2(acc23[xi], w2b, qp[xi + 2]);
            }
        }
    }

    #pragma unroll
    for (int xi = 0; xi < 8; xi++) {
        float2 a = unpackf2(acc01[xi]);
        float2 c = unpackf2(acc23[xi]);
        float4 o = make_float4(a.x, a.y, c.x, c.y);
        *reinterpret_cast<float4*>(
            &g_t[((size_t)(b*HH + y)*WW + x0 + xi) * NC + g*GC + oc]) = o;
    }
}

// ---------------------------------------------------------------------------
// Fused: LayerNorm + erf-GELU + offset proj + tanh*range + ref grid + sample.
// ---------------------------------------------------------------------------
__global__ __launch_bounds__(384) void ln_sample_kernel(
    const float* __restrict__ ln_g, const float* __restrict__ ln_b,
    const float* __restrict__ wp, const float* __restrict__ x)
{
    const int p   = blockIdx.x;
    const int tid = threadIdx.x;
    const int wid  = tid >> 5;
    const int lane = tid & 31;

    float v = g_t[(size_t)p * NC + tid];

    __shared__ float red[2][12];
    __shared__ float sv[NC];
    __shared__ float spos[12];

    float s = v, sq = v * v;
    #pragma unroll
    for (int o = 16; o > 0; o >>= 1) {
        s  += __shfl_xor_sync(0xffffffffu, s,  o);
        sq += __shfl_xor_sync(0xffffffffu, sq, o);
    }
    if (lane == 0) { red[0][wid] = s; red[1][wid] = sq; }
    __syncthreads();
    if (tid < 32) {
        float a = (tid < 12) ? red[0][tid] : 0.f;
        float c = (tid < 12) ? red[1][tid] : 0.f;
        #pragma unroll
        for (int o = 8; o > 0; o >>= 1) {
            a += __shfl_xor_sync(0xffffffffu, a, o);
            c += __shfl_xor_sync(0xffffffffu, c, o);
        }
        if (tid == 0) { red[0][0] = a; red[1][0] = c; }
    }
    __syncthreads();
    const float mu  = red[0][0] * (1.f / NC);
    const float var = red[1][0] * (1.f / NC) - mu * mu;
    float nv = (v - mu) * rsqrtf(var + 1e-3f) * ln_g[tid] + ln_b[tid];
    nv = 0.5f * nv * (1.f + erff(nv * 0.70710678118654752f));

    sv[tid] = nv;
    __syncthreads();

    const int grp = wid >> 1, comp = wid & 1;
    float part = sv[grp*GC + lane]      * wp[lane * 2 + comp]
               + sv[grp*GC + 32 + lane] * wp[(32 + lane) * 2 + comp];
    #pragma unroll
    for (int o = 16; o > 0; o >>= 1)
        part += __shfl_xor_sync(0xffffffffu, part, o);

    const int pix = p & 1023;
    if (lane == 0) {
        const int yy = pix >> 5, xx = pix & 31;
        float refv = (comp == 0) ? (float)xx : (float)yy;
        spos[grp*2 + comp] = tanhf(part) * 16.f + refv;
    }
    __syncthreads();

    const int b = p >> 10;
    const int g = tid >> 6, c = tid & 63;
    const float p0 = spos[g*2 + 0];
    const float p1 = spos[g*2 + 1];
    const float xqf = p1 + 1.f;
    const float yqf = p0 + 1.f;
    const float x0f = fminf(fmaxf(floorf(xqf), 0.f), 32.f);
    const float y0f = fminf(fmaxf(floorf(yqf), 0.f), 32.f);
    const float ax = fminf(fmaxf(xqf - x0f, 0.f), 1.f);
    const float ay = fminf(fmaxf(yqf - y0f, 0.f), 1.f);
    const int x0 = (int)x0f, y0 = (int)y0f;

    const size_t choff = (size_t)g * GC + c;
    auto fetch = [&](int yy2, int xx2) -> float {
        if (yy2 < 1 || yy2 > 32 || xx2 < 1 || xx2 > 32) return 0.f;
        return x[((size_t)(b*HH + (yy2-1)) * WW + (xx2-1)) * NC + choff];
    };
    float tl = fetch(y0,     x0);
    float tr = fetch(y0,     x0 + 1);
    float bl = fetch(y0 + 1, x0);
    float br = fetch(y0 + 1, x0 + 1);
    float top = tl + ax * (tr - tl);
    float bot = bl + ax * (br - bl);
    g_xs[((size_t)b * NPIX + pix) * NC + choff] = top + ay * (bot - top);
}

// ---------------------------------------------------------------------------
// Launch
// ---------------------------------------------------------------------------
extern "C" void kernel_launch(void* const* d_in, const int* in_sizes, int n_in,
                              void* d_out, int out_size)
{
    const float* x      = (const float*)d_in[0];
    const float* w_q    = (const float*)d_in[1];
    const float* b_q    = (const float*)d_in[2];
    const float* w_off0 = (const float*)d_in[3];
    const float* b_off0 = (const float*)d_in[4];
    const float* ln_g   = (const float*)d_in[5];
    const float* ln_b   = (const float*)d_in[6];
    const float* w_offp = (const float*)d_in[7];
    const float* w_k    = (const float*)d_in[8];
    const float* b_k    = (const float*)d_in[9];
    const float* w_v    = (const float*)d_in[10];
    const float* b_v    = (const float*)d_in[11];
    const float* w_o    = (const float*)d_in[12];
    const float* b_o    = (const float*)d_in[13];
    float* out = (float*)d_out;

    float *pq, *pxs, *pk, *pv, *po;
    cudaGetSymbolAddress((void**)&pq,  g_q);
    cudaGetSymbolAddress((void**)&pxs, g_xs);
    cudaGetSymbolAddress((void**)&pk,  g_k);
    cudaGetSymbolAddress((void**)&pv,  g_v);
    cudaGetSymbolAddress((void**)&po,  g_o);

    cudaFuncSetAttribute(attn_mma_kernel,
                         cudaFuncAttributeMaxDynamicSharedMemorySize, ATTN_SMEM);
    cudaFuncSetAttribute(gemm_mma3_kernel,
                         cudaFuncAttributeMaxDynamicSharedMemorySize, GEMM_SMEM);
    cudaFuncSetAttribute(gemm_mma_kernel,
                         cudaFuncAttributeMaxDynamicSharedMemorySize, GEMM_SMEM);
    cudaFuncSetAttribute(gemm_kv_kernel,
                         cudaFuncAttributeMaxDynamicSharedMemorySize, GEMM_SMEM);
    cudaFuncSetAttribute(conv_off_kernel,
                         cudaFuncAttributeMaxDynamicSharedMemorySize, CONV_SMEM);

    dim3 ggrid(MTOT / 128, NC / 128);
    dim3 kvgrid(MTOT / 128, NC / 128, 2);
    dim3 agrid(NPIX / 128, HEADS, BB);

    // 1. q = x @ w_q + b_q   (3xTF32 compensated, cp.async pipelined)
    gemm_mma3_kernel<<<ggrid, 256, GEMM_SMEM>>>(x, w_q, b_q, pq);
    // 2. grouped 3x3 conv on q -> g_t
    conv_off_kernel<<<BB * 8 * GROUPS, 256, CONV_SMEM>>>(w_off0, b_off0);
    // 3. LN + GELU + offset proj + tanh + ref + bilinear sample -> g_xs
    ln_sample_kernel<<<MTOT, NC>>>(ln_g, ln_b, w_offp, x);
    // 4. fused k+v projections (tf32 cp.async — R11 config)
    gemm_kv_kernel<<<kvgrid, 256, GEMM_SMEM>>>(pxs, w_k, b_k, pk, w_v, b_v, pv);
    // 5. attention (fp16 m16n8k16 flash, register-resident P) -> g_o
    attn_mma_kernel<<<agrid, 256, ATTN_SMEM>>>();
    // 6. y = o @ w_o + b_o -> d_out (tf32 cp.async — R11 config)
    gemm_mma_kernel<<<ggrid, 256, GEMM_SMEM>>>(po, w_o, b_o, out);
}

// round 16
// speedup vs baseline: 1.0741x; 1.0047x over previous
#include <cuda_runtime.h>
#include <cuda_fp16.h>
#include <math.h>
#include <stdint.h>

// ---------------------------------------------------------------------------
// Problem constants
// ---------------------------------------------------------------------------
#define BB     8
#define HH     32
#define WW     32
#define NC     384
#define GROUPS 6
#define HEADS  12
#define HC     32
#define GC     64
#define NPIX   (HH*WW)          // 1024
#define MTOT   (BB*NPIX)        // 8192
#define NCH    12               // K chunks of 32

// ---------------------------------------------------------------------------
// Scratch (static device globals — no allocation allowed)
// ---------------------------------------------------------------------------
__device__ float g_q  [MTOT*NC];
__device__ float g_t  [MTOT*NC];
__device__ float g_xs [MTOT*NC];
__device__ float g_k  [MTOT*NC];
__device__ float g_v  [MTOT*NC];
__device__ float g_o  [MTOT*NC];

// ---------------------------------------------------------------------------
// mma.sync / packed-f32x2 / cp.async helpers (base sm_103 ISA)
// ---------------------------------------------------------------------------
__device__ __forceinline__ uint32_t f2tf32(float x) {
    uint32_t r;
    asm("cvt.rna.tf32.f32 %0, %1;" : "=r"(r) : "f"(x));
    return r;
}
__device__ __forceinline__ float ex2f(float x) {
    float r;
    asm("ex2.approx.f32 %0, %1;" : "=f"(r) : "f"(x));
    return r;
}
__device__ __forceinline__ uint32_t f16x2(float lo, float hi) {
    uint32_t r;
    asm("cvt.rn.f16x2.f32 %0, %1, %2;" : "=r"(r) : "f"(hi), "f"(lo));
    return r;
}
__device__ __forceinline__ uint16_t f16b(float x) {
    uint16_t r;
    asm("cvt.rn.f16.f32 %0, %1;" : "=h"(r) : "f"(x));
    return r;
}
__device__ __forceinline__ void mma_tf32(float* c, const uint32_t* a, const uint32_t* b) {
    asm volatile(
        "mma.sync.aligned.m16n8k8.row.col.f32.tf32.tf32.f32 "
        "{%0,%1,%2,%3}, {%4,%5,%6,%7}, {%8,%9}, {%0,%1,%2,%3};"
        : "+f"(c[0]), "+f"(c[1]), "+f"(c[2]), "+f"(c[3])
        : "r"(a[0]), "r"(a[1]), "r"(a[2]), "r"(a[3]), "r"(b[0]), "r"(b[1]));
}
__device__ __forceinline__ void mma_f16(float* c, const uint32_t* a, const uint32_t* b) {
    asm volatile(
        "mma.sync.aligned.m16n8k16.row.col.f32.f16.f16.f32 "
        "{%0,%1,%2,%3}, {%4,%5,%6,%7}, {%8,%9}, {%0,%1,%2,%3};"
        : "+f"(c[0]), "+f"(c[1]), "+f"(c[2]), "+f"(c[3])
        : "r"(a[0]), "r"(a[1]), "r"(a[2]), "r"(a[3]), "r"(b[0]), "r"(b[1]));
}
#define FMA2(d, a, b) \
    asm("fma.rn.f32x2 %0, %1, %2, %0;" : "+l"(d) : "l"(a), "l"(b))
__device__ __forceinline__ uint64_t packf2(float lo, float hi) {
    uint64_t r;
    asm("mov.b64 %0, {%1, %2};" : "=l"(r) : "f"(lo), "f"(hi));
    return r;
}
__device__ __forceinline__ float2 unpackf2(uint64_t v) {
    float2 r;
    asm("mov.b64 {%0, %1}, %2;" : "=f"(r.x), "=f"(r.y) : "l"(v));
    return r;
}
__device__ __forceinline__ void cp16(uint32_t saddr, const void* gptr) {
    asm volatile("cp.async.ca.shared.global [%0], [%1], 16;"
                 :: "r"(saddr), "l"(gptr));
}
#define CP_COMMIT() asm volatile("cp.async.commit_group;" ::: "memory")
#define CP_WAIT0()  asm volatile("cp.async.wait_group 0;"  ::: "memory")

// single dynamic-smem symbol for the whole TU
extern __shared__ uint32_t dynsm[];

// ---------------------------------------------------------------------------
// Pipelined tf32 mma GEMM (R11-proven): 256 thr, warp tile 32x64, cp.async
// double-buffered raw fp32 tiles, cvt at fragment load.
// ---------------------------------------------------------------------------
#define GSA 36
#define GSB 136
#define GEMM_SMEM ((2*128*GSA + 2*32*GSB) * 4)

__device__ __forceinline__ void gemm_body_v3(
    const float* __restrict__ A, const float* __restrict__ W,
    const float* __restrict__ bias, float* __restrict__ C)
{
    float* As = reinterpret_cast<float*>(dynsm);
    float* Bs = As + 2 * 128 * GSA;
    const uint32_t sA = (uint32_t)__cvta_generic_to_shared(As);
    const uint32_t sB = (uint32_t)__cvta_generic_to_shared(Bs);

    const int tid = threadIdx.x, lane = tid & 31, wid = tid >> 5;
    const int wm = wid & 3, wn = wid >> 2;
    const int bm = blockIdx.x * 128, bn = blockIdx.y * 128;
    const int lq = lane >> 2, lr = lane & 3;

    float acc[2][8][4];
    #pragma unroll
    for (int i = 0; i < 2; i++)
        #pragma unroll
        for (int j = 0; j < 8; j++)
            #pragma unroll
            for (int t = 0; t < 4; t++) acc[i][j][t] = 0.f;

    auto stage = [&](int c, int buf) {
        #pragma unroll
        for (int l = 0; l < 4; l++) {
            int idx = tid + l * 256;
            int ra = idx >> 3, ca = idx & 7;
            cp16(sA + (buf * 128 * GSA + ra * GSA + ca * 4) * 4,
                 &A[(size_t)(bm + ra) * NC + c * 32 + ca * 4]);
            int rb = idx >> 5, cb = idx & 31;
            cp16(sB + (buf * 32 * GSB + rb * GSB + cb * 4) * 4,
                 &W[(size_t)(c * 32 + rb) * NC + bn + cb * 4]);
        }
        CP_COMMIT();
    };

    stage(0, 0);
    CP_WAIT0();
    __syncthreads();

    for (int c = 0; c < NCH; c++) {
        const int buf = c & 1;
        const bool more = (c + 1 < NCH);
        if (more) stage(c + 1, buf ^ 1);

        const float* Ab = As + buf * 128 * GSA;
        const float* Bb = Bs + buf * 32 * GSB;
        #pragma unroll
        for (int ks = 0; ks < 4; ks++) {
            const int k0 = ks * 8;
            uint32_t af[2][4];
            #pragma unroll
            for (int i = 0; i < 2; i++) {
                const int rb = wm * 32 + i * 16;
                af[i][0] = f2tf32(Ab[(rb +     lq) * GSA + k0 +     lr]);
                af[i][1] = f2tf32(Ab[(rb + 8 + lq) * GSA + k0 +     lr]);
                af[i][2] = f2tf32(Ab[(rb +     lq) * GSA + k0 + 4 + lr]);
                af[i][3] = f2tf32(Ab[(rb + 8 + lq) * GSA + k0 + 4 + lr]);
            }
            #pragma unroll
            for (int j = 0; j < 8; j++) {
                uint32_t bf[2];
                const int col = wn * 64 + j * 8 + lq;
                bf[0] = f2tf32(Bb[(k0 +     lr) * GSB + col]);
                bf[1] = f2tf32(Bb[(k0 + 4 + lr) * GSB + col]);
                mma_tf32(acc[0][j], af[0], bf);
                mma_tf32(acc[1][j], af[1], bf);
            }
        }
        if (more) CP_WAIT0();
        __syncthreads();
    }

    #pragma unroll
    for (int j = 0; j < 8; j++) {
        const int col = bn + wn * 64 + j * 8 + lr * 2;
        const float b0 = bias[col], b1 = bias[col + 1];
        #pragma unroll
        for (int i = 0; i < 2; i++) {
            const int r0 = bm + wm * 32 + i * 16 + lq;
            *reinterpret_cast<float2*>(&C[(size_t)r0 * NC + col]) =
                make_float2(acc[i][j][0] + b0, acc[i][j][1] + b1);
            *reinterpret_cast<float2*>(&C[(size_t)(r0 + 8) * NC + col]) =
                make_float2(acc[i][j][2] + b0, acc[i][j][3] + b1);
        }
    }
}

__global__ __launch_bounds__(256) void gemm_mma_kernel(
    const float* __restrict__ A, const float* __restrict__ W,
    const float* __restrict__ bias, float* __restrict__ C)
{
    gemm_body_v3(A, W, bias, C);
}

__global__ __launch_bounds__(256) void gemm_kv_kernel(
    const float* __restrict__ A,
    const float* __restrict__ Wk, const float* __restrict__ bk, float* __restrict__ K,
    const float* __restrict__ Wv, const float* __restrict__ bv, float* __restrict__ V)
{
    if (blockIdx.z == 0)
        gemm_body_v3(A, Wk, bk, K);
    else
        gemm_body_v3(A, Wv, bv, V);
}

// ---------------------------------------------------------------------------
// 3xTF32 compensated GEMM (near-fp32) — q projection only. Exact R11 version
// (serial staging-time hi/lo split — the pipelined variant measured slower).
// ---------------------------------------------------------------------------
#define G3_SMEM ((128*GSA*2 + 32*GSB*2) * 4)

__global__ __launch_bounds__(256) void gemm_mma3_kernel(
    const float* __restrict__ A, const float* __restrict__ W,
    const float* __restrict__ bias, float* __restrict__ C)
{
    uint32_t* s3 = dynsm;
    uint32_t* AsH = s3;
    uint32_t* AsL = s3 + 128 * GSA;
    uint32_t* BsH = s3 + 2 * 128 * GSA;
    uint32_t* BsL = BsH + 32 * GSB;

    const int tid = threadIdx.x, lane = tid & 31, wid = tid >> 5;
    const int wm = wid & 3, wn = wid >> 2;
    const int bm = blockIdx.x * 128, bn = blockIdx.y * 128;
    const int lq = lane >> 2, lr = lane & 3;

    float acc[2][8][4];
    #pragma unroll
    for (int i = 0; i < 2; i++)
        #pragma unroll
        for (int j = 0; j < 8; j++)
            #pragma unroll
            for (int t = 0; t < 4; t++) acc[i][j][t] = 0.f;

    for (int c = 0; c < NCH; c++) {
        #pragma unroll
        for (int l = 0; l < 4; l++) {
            int idx = tid + l * 256;
            int row = idx >> 3, c4 = idx & 7;
            float4 v = *reinterpret_cast<const float4*>(
                &A[(size_t)(bm + row) * NC + c * 32 + c4 * 4]);
            uint32_t* dh = &AsH[row * GSA + c4 * 4];
            uint32_t* dl = &AsL[row * GSA + c4 * 4];
            uint32_t h;
            h = f2tf32(v.x); dh[0] = h; dl[0] = f2tf32(v.x - __uint_as_float(h));
            h = f2tf32(v.y); dh[1] = h; dl[1] = f2tf32(v.y - __uint_as_float(h));
            h = f2tf32(v.z); dh[2] = h; dl[2] = f2tf32(v.z - __uint_as_float(h));
            h = f2tf32(v.w); dh[3] = h; dl[3] = f2tf32(v.w - __uint_as_float(h));
        }
        #pragma unroll
        for (int l = 0; l < 4; l++) {
            int idx = tid + l * 256;
            int row = idx >> 5, c4 = idx & 31;
            float4 v = *reinterpret_cast<const float4*>(
                &W[(size_t)(c * 32 + row) * NC + bn + c4 * 4]);
            uint32_t* dh = &BsH[row * GSB + c4 * 4];
            uint32_t* dl = &BsL[row * GSB + c4 * 4];
            uint32_t h;
            h = f2tf32(v.x); dh[0] = h; dl[0] = f2tf32(v.x - __uint_as_float(h));
            h = f2tf32(v.y); dh[1] = h; dl[1] = f2tf32(v.y - __uint_as_float(h));
            h = f2tf32(v.z); dh[2] = h; dl[2] = f2tf32(v.z - __uint_as_float(h));
            h = f2tf32(v.w); dh[3] = h; dl[3] = f2tf32(v.w - __uint_as_float(h));
        }
        __syncthreads();
        #pragma unroll
        for (int ks = 0; ks < 4; ks++) {
            const int k0 = ks * 8;
            uint32_t afh[2][4], afl[2][4];
            #pragma unroll
            for (int i = 0; i < 2; i++) {
                const int rb = wm * 32 + i * 16;
                afh[i][0] = AsH[(rb +     lq) * GSA + k0 +     lr];
                afh[i][1] = AsH[(rb + 8 + lq) * GSA + k0 +     lr];
                afh[i][2] = AsH[(rb +     lq) * GSA + k0 + 4 + lr];
                afh[i][3] = AsH[(rb + 8 + lq) * GSA + k0 + 4 + lr];
                afl[i][0] = AsL[(rb +     lq) * GSA + k0 +     lr];
                afl[i][1] = AsL[(rb + 8 + lq) * GSA + k0 +     lr];
                afl[i][2] = AsL[(rb +     lq) * GSA + k0 + 4 + lr];
                afl[i][3] = AsL[(rb + 8 + lq) * GSA + k0 + 4 + lr];
            }
            #pragma unroll
            for (int j = 0; j < 8; j++) {
                uint32_t bfh[2], bfl[2];
                const int col = wn * 64 + j * 8 + lq;
                bfh[0] = BsH[(k0 +     lr) * GSB + col];
                bfh[1] = BsH[(k0 + 4 + lr) * GSB + col];
                bfl[0] = BsL[(k0 +     lr) * GSB + col];
                bfl[1] = BsL[(k0 + 4 + lr) * GSB + col];
                #pragma unroll
                for (int i = 0; i < 2; i++) {
                    mma_tf32(acc[i][j], afl[i], bfh);
                    mma_tf32(acc[i][j], afh[i], bfl);
                    mma_tf32(acc[i][j], afh[i], bfh);
                }
            }
        }
        __syncthreads();
    }
    #pragma unroll
    for (int j = 0; j < 8; j++) {
        const int col = bn + wn * 64 + j * 8 + lr * 2;
        const float b0 = bias[col], b1 = bias[col + 1];
        #pragma unroll
        for (int i = 0; i < 2; i++) {
            const int r0 = bm + wm * 32 + i * 16 + lq;
            *reinterpret_cast<float2*>(&C[(size_t)r0 * NC + col]) =
                make_float2(acc[i][j][0] + b0, acc[i][j][1] + b1);
            *reinterpret_cast<float2*>(&C[(size_t)(r0 + 8) * NC + col]) =
                make_float2(acc[i][j][2] + b0, acc[i][j][3] + b1);
        }
    }
}

// ---------------------------------------------------------------------------
// Flash attention v4 (R11-proven): fp16 m16n8k16, fixed-max softmax,
// register-resident P, double-buffered fp16 K/V via register prefetch.
// ---------------------------------------------------------------------------
#define KW  20
#define VTW 36
#define ATTN_SMEM (2*64*KW*4 + 2*32*VTW*4)

__global__ __launch_bounds__(256) void attn_mma_kernel()
{
    uint32_t* Khw = dynsm;
    uint32_t* Vtw = dynsm + 2 * 64 * KW;

    const int tid = threadIdx.x, lane = tid & 31, wid = tid >> 5;
    const int lq = lane >> 2, lr = lane & 3;
    const int qt = blockIdx.x, h = blockIdx.y, b = blockIdx.z;
    const int q0 = qt * 128;

    const float qscale = 0.17677669529663689f * 1.4426950408889634f;
    uint32_t* Qw = dynsm;
    #pragma unroll
    for (int l = 0; l < 4; l++) {
        int idx = tid + l * 256;
        int row = idx >> 3, c4 = idx & 7;
        float4 v = *reinterpret_cast<const float4*>(
            &g_q[((size_t)b * NPIX + q0 + row) * NC + h * HC + c4 * 4]);
        Qw[row * KW + c4 * 2 + 0] = f16x2(v.x * qscale, v.y * qscale);
        Qw[row * KW + c4 * 2 + 1] = f16x2(v.z * qscale, v.w * qscale);
    }
    __syncthreads();
    uint32_t qf[2][4];
    {
        const int rb = wid * 16;
        #pragma unroll
        for (int ks = 0; ks < 2; ks++) {
            qf[ks][0] = Qw[(rb +     lq) * KW + lr +     8 * ks];
            qf[ks][1] = Qw[(rb + 8 + lq) * KW + lr +     8 * ks];
            qf[ks][2] = Qw[(rb +     lq) * KW + lr + 4 + 8 * ks];
            qf[ks][3] = Qw[(rb + 8 + lq) * KW + lr + 4 + 8 * ks];
        }
    }
    __syncthreads();

    float o[4][4];
    #pragma unroll
    for (int j = 0; j < 4; j++)
        #pragma unroll
        for (int t = 0; t < 4; t++) o[j][t] = 0.f;
    float l0 = 0.f, l1 = 0.f;

    auto ldtile = [&](int kt, float4* rk, float4* rv) {
        #pragma unroll
        for (int l = 0; l < 2; l++) {
            int idx = tid + l * 256;
            int key = idx >> 3, c4 = idx & 7;
            size_t base = ((size_t)b * NPIX + kt + key) * NC + h * HC + c4 * 4;
            rk[l] = *reinterpret_cast<const float4*>(&g_k[base]);
            rv[l] = *reinterpret_cast<const float4*>(&g_v[base]);
        }
    };
    auto sttile = [&](int buf, const float4* rk, const float4* rv) {
        uint32_t* K = Khw + buf * 64 * KW;
        uint16_t* Vt = reinterpret_cast<uint16_t*>(Vtw + buf * 32 * VTW);
        #pragma unroll
        for (int l = 0; l < 2; l++) {
            int idx = tid + l * 256;
            int key = idx >> 3, c4 = idx & 7;
            K[key * KW + c4 * 2 + 0] = f16x2(rk[l].x, rk[l].y);
            K[key * KW + c4 * 2 + 1] = f16x2(rk[l].z, rk[l].w);
            Vt[(c4 * 4 + 0) * (2 * VTW) + key] = f16b(rv[l].x);
            Vt[(c4 * 4 + 1) * (2 * VTW) + key] = f16b(rv[l].y);
            Vt[(c4 * 4 + 2) * (2 * VTW) + key] = f16b(rv[l].z);
            Vt[(c4 * 4 + 3) * (2 * VTW) + key] = f16b(rv[l].w);
        }
    };

    {
        float4 rk[2], rv[2];
        ldtile(0, rk, rv);
        sttile(0, rk, rv);
    }
    __syncthreads();

    for (int it = 0; it < 16; it++) {
        const int buf = it & 1;
        const bool more = (it < 15);
        float4 rk[2], rv[2];
        if (more) ldtile((it + 1) * 64, rk, rv);

        const uint32_t* K = Khw + buf * 64 * KW;
        const uint32_t* V = Vtw + buf * 32 * VTW;

        float s[8][4];
        #pragma unroll
        for (int j = 0; j < 8; j++)
            #pragma unroll
            for (int t = 0; t < 4; t++) s[j][t] = 0.f;
        #pragma unroll
        for (int ks = 0; ks < 2; ks++) {
            #pragma unroll
            for (int j = 0; j < 8; j++) {
                uint32_t bf[2];
                const int col = j * 8 + lq;
                bf[0] = K[col * KW + lr +     8 * ks];
                bf[1] = K[col * KW + lr + 4 + 8 * ks];
                mma_f16(s[j], qf[ks], bf);
            }
        }

        #pragma unroll
        for (int j = 0; j < 8; j++) {
            s[j][0] = ex2f(s[j][0]);
            s[j][1] = ex2f(s[j][1]);
            s[j][2] = ex2f(s[j][2]);
            s[j][3] = ex2f(s[j][3]);
            l0 += s[j][0] + s[j][1];
            l1 += s[j][2] + s[j][3];
        }

        if (more) sttile(buf ^ 1, rk, rv);

        #pragma unroll
        for (int ks = 0; ks < 4; ks++) {
            uint32_t ap[4];
            ap[0] = f16x2(s[2*ks    ][0], s[2*ks    ][1]);
            ap[1] = f16x2(s[2*ks    ][2], s[2*ks    ][3]);
            ap[2] = f16x2(s[2*ks + 1][0], s[2*ks + 1][1]);
            ap[3] = f16x2(s[2*ks + 1][2], s[2*ks + 1][3]);
            #pragma unroll
            for (int j = 0; j < 4; j++) {
                uint32_t bf[2];
                const int n = j * 8 + lq;
                bf[0] = V[n * VTW + lr +     8 * ks];
                bf[1] = V[n * VTW + lr + 4 + 8 * ks];
                mma_f16(o[j], ap, bf);
            }
        }
        __syncthreads();
    }

    l0 += __shfl_xor_sync(0xffffffffu, l0, 1);
    l0 += __shfl_xor_sync(0xffffffffu, l0, 2);
    l1 += __shfl_xor_sync(0xffffffffu, l1, 1);
    l1 += __shfl_xor_sync(0xffffffffu, l1, 2);
    const float il0 = 1.f / l0, il1 = 1.f / l1;
    const int rg = q0 + wid * 16 + lq;
    #pragma unroll
    for (int j = 0; j < 4; j++) {
        const int col = h * HC + j * 8 + lr * 2;
        *reinterpret_cast<float2*>(&g_o[((size_t)b * NPIX + rg) * NC + col]) =
            make_float2(o[j][0] * il0, o[j][1] * il0);
        *reinterpret_cast<float2*>(&g_o[((size_t)b * NPIX + rg + 8) * NC + col]) =
            make_float2(o[j][2] * il1, o[j][3] * il1);
    }
}

// ---------------------------------------------------------------------------
// Grouped 3x3 conv (packed fma.rn.f32x2, bit-exact fp32) — unchanged.
// ---------------------------------------------------------------------------
#define CONV_SMEM (64 * 6 * 36 * 4)

__global__ __launch_bounds__(256) void conv_off_kernel(
    const float* __restrict__ W, const float* __restrict__ bias)
{
    float* qs = reinterpret_cast<float*>(dynsm);
    const int bid = blockIdx.x;
    const int g  = bid % GROUPS;
    const int yt = (bid / GROUPS) & 7;
    const int b  = bid / (GROUPS * 8);
    const int y0 = yt * 4;
    const int tid = threadIdx.x;

    for (int i = tid; i < 64 * 6 * 34; i += 256) {
        int c  = i & 63;
        int xx = (i >> 6) % 34;
        int r  = i / (64 * 34);
        int yy = y0 + r - 1;
        float v = 0.f;
        if (xx >= 1 && xx <= 32 && yy >= 0 && yy < HH)
            v = g_q[((size_t)(b*HH + yy)*WW + (xx-1)) * NC + g*GC + c];
        qs[(c * 6 + r) * 36 + xx] = v;
    }
    __syncthreads();

    const int ty = tid >> 6;
    const int x0 = ((tid >> 4) & 3) * 8;
    const int oc = (tid & 15) * 4;
    const int y  = y0 + ty;

    uint64_t acc01[8], acc23[8];
    {
        float4 bv = *reinterpret_cast<const float4*>(&bias[g*GC + oc]);
        uint64_t b01 = packf2(bv.x, bv.y), b23 = packf2(bv.z, bv.w);
        #pragma unroll
        for (int xi = 0; xi < 8; xi++) { acc01[xi] = b01; acc23[xi] = b23; }
    }

    #pragma unroll
    for (int dy = 0; dy < 3; dy++) {
        const int r = ty + dy;
        #pragma unroll 2
        for (int ic = 0; ic < GC; ic++) {
            const float* qrow = &qs[(ic * 6 + r) * 36 + x0];
            uint64_t qp[10];
            #pragma unroll
            for (int j = 0; j < 10; j++) {
                float qv = qrow[j];
                qp[j] = packf2(qv, qv);
            }
            const uint64_t* wp0 = reinterpret_cast<const uint64_t*>(
                &W[(size_t)((dy*3 + 0) * GC + ic) * NC + g*GC + oc]);
            const uint64_t* wp1 = reinterpret_cast<const uint64_t*>(
                &W[(size_t)((dy*3 + 1) * GC + ic) * NC + g*GC + oc]);
            const uint64_t* wp2 = reinterpret_cast<const uint64_t*>(
                &W[(size_t)((dy*3 + 2) * GC + ic) * NC + g*GC + oc]);
            const uint64_t w0a = wp0[0], w0b = wp0[1];
            const uint64_t w1a = wp1[0], w1b = wp1[1];
            const uint64_t w2a = wp2[0], w2b = wp2[1];
            #pragma unroll
            for (int xi = 0; xi < 8; xi++) {
                FMA2(acc01[xi], w0a, qp[xi]);
                FMA2(acc23[xi], w0b, qp[xi]);
                FMA2(acc01[xi], w1a, qp[xi + 1]);
                FMA2(acc23[xi], w1b, qp[xi + 1]);
                FMA2(acc01[xi], w2a, qp[xi + 2]);
                FMA2(acc23[xi], w2b, qp[xi + 2]);
            }
        }
    }

    #pragma unroll
    for (int xi = 0; xi < 8; xi++) {
        float2 a = unpackf2(acc01[xi]);
        float2 c = unpackf2(acc23[xi]);
        float4 o = make_float4(a.x, a.y, c.x, c.y);
        *reinterpret_cast<float4*>(
            &g_t[((size_t)(b*HH + y)*WW + x0 + xi) * NC + g*GC + oc]) = o;
    }
}

// ---------------------------------------------------------------------------
// Fused LN + erf-GELU + offset proj + tanh*range + ref grid + sample,
// v2: TWO pixels per block (768 thr; warps 0-11 = pixel 0, 12-23 = pixel 1).
// Per-pixel math bit-identical to v1; halves block count.
// ---------------------------------------------------------------------------
__global__ __launch_bounds__(768) void ln_sample_kernel(
    const float* __restrict__ ln_g, const float* __restrict__ ln_b,
    const float* __restrict__ wp, const float* __restrict__ x)
{
    const int tid = threadIdx.x;
    const int px  = tid / NC;            // 0 or 1
    const int t   = tid - px * NC;       // 0..383
    const int p   = blockIdx.x * 2 + px;
    const int wid  = t >> 5;             // 0..11 within pixel group
    const int lane = t & 31;

    float v = g_t[(size_t)p * NC + t];

    __shared__ float red[2][2][12];
    __shared__ float sv[2][NC];
    __shared__ float spos[2][12];

    float s = v, sq = v * v;
    #pragma unroll
    for (int o = 16; o > 0; o >>= 1) {
        s  += __shfl_xor_sync(0xffffffffu, s,  o);
        sq += __shfl_xor_sync(0xffffffffu, sq, o);
    }
    if (lane == 0) { red[px][0][wid] = s; red[px][1][wid] = sq; }
    __syncthreads();
    if (t < 32) {   // warp 0 of each pixel group
        float a = (t < 12) ? red[px][0][t] : 0.f;
        float c = (t < 12) ? red[px][1][t] : 0.f;
        #pragma unroll
        for (int o = 8; o > 0; o >>= 1) {
            a += __shfl_xor_sync(0xffffffffu, a, o);
            c += __shfl_xor_sync(0xffffffffu, c, o);
        }
        if (t == 0) { red[px][0][0] = a; red[px][1][0] = c; }
    }
    __syncthreads();
    const float mu  = red[px][0][0] * (1.f / NC);
    const float var = red[px][1][0] * (1.f / NC) - mu * mu;
    float nv = (v - mu) * rsqrtf(var + 1e-3f) * ln_g[t] + ln_b[t];
    nv = 0.5f * nv * (1.f + erff(nv * 0.70710678118654752f));

    sv[px][t] = nv;
    __syncthreads();

    const int grp = wid >> 1, comp = wid & 1;
    float part = sv[px][grp*GC + lane]      * wp[lane * 2 + comp]
               + sv[px][grp*GC + 32 + lane] * wp[(32 + lane) * 2 + comp];
    #pragma unroll
    for (int o = 16; o > 0; o >>= 1)
        part += __shfl_xor_sync(0xffffffffu, part, o);

    const int pix = p & 1023;
    if (lane == 0) {
        const int yy = pix >> 5, xx = pix & 31;
        float refv = (comp == 0) ? (float)xx : (float)yy;
        spos[px][grp*2 + comp] = tanhf(part) * 16.f + refv;
    }
    __syncthreads();

    const int b = p >> 10;
    const int g = t >> 6, c = t & 63;
    const float p0 = spos[px][g*2 + 0];
    const float p1 = spos[px][g*2 + 1];
    const float xqf = p1 + 1.f;
    const float yqf = p0 + 1.f;
    const float x0f = fminf(fmaxf(floorf(xqf), 0.f), 32.f);
    const float y0f = fminf(fmaxf(floorf(yqf), 0.f), 32.f);
    const float ax = fminf(fmaxf(xqf - x0f, 0.f), 1.f);
    const float ay = fminf(fmaxf(yqf - y0f, 0.f), 1.f);
    const int x0 = (int)x0f, y0 = (int)y0f;

    const size_t choff = (size_t)g * GC + c;
    auto fetch = [&](int yy2, int xx2) -> float {
        if (yy2 < 1 || yy2 > 32 || xx2 < 1 || xx2 > 32) return 0.f;
        return x[((size_t)(b*HH + (yy2-1)) * WW + (xx2-1)) * NC + choff];
    };
    float tl = fetch(y0,     x0);
    float tr = fetch(y0,     x0 + 1);
    float bl = fetch(y0 + 1, x0);
    float br = fetch(y0 + 1, x0 + 1);
    float top = tl + ax * (tr - tl);
    float bot = bl + ax * (br - bl);
    g_xs[((size_t)b * NPIX + pix) * NC + choff] = top + ay * (bot - top);
}

// ---------------------------------------------------------------------------
// Launch
// ---------------------------------------------------------------------------
extern "C" void kernel_launch(void* const* d_in, const int* in_sizes, int n_in,
                              void* d_out, int out_size)
{
    const float* x      = (const float*)d_in[0];
    const float* w_q    = (const float*)d_in[1];
    const float* b_q    = (const float*)d_in[2];
    const float* w_off0 = (const float*)d_in[3];
    const float* b_off0 = (const float*)d_in[4];
    const float* ln_g   = (const float*)d_in[5];
    const float* ln_b   = (const float*)d_in[6];
    const float* w_offp = (const float*)d_in[7];
    const float* w_k    = (const float*)d_in[8];
    const float* b_k    = (const float*)d_in[9];
    const float* w_v    = (const float*)d_in[10];
    const float* b_v    = (const float*)d_in[11];
    const float* w_o    = (const float*)d_in[12];
    const float* b_o    = (const float*)d_in[13];
    float* out = (float*)d_out;

    float *pq, *pxs, *pk, *pv, *po;
    cudaGetSymbolAddress((void**)&pq,  g_q);
    cudaGetSymbolAddress((void**)&pxs, g_xs);
    cudaGetSymbolAddress((void**)&pk,  g_k);
    cudaGetSymbolAddress((void**)&pv,  g_v);
    cudaGetSymbolAddress((void**)&po,  g_o);

    cudaFuncSetAttribute(attn_mma_kernel,
                         cudaFuncAttributeMaxDynamicSharedMemorySize, ATTN_SMEM);
    cudaFuncSetAttribute(gemm_mma3_kernel,
                         cudaFuncAttributeMaxDynamicSharedMemorySize, G3_SMEM);
    cudaFuncSetAttribute(gemm_mma_kernel,
                         cudaFuncAttributeMaxDynamicSharedMemorySize, GEMM_SMEM);
    cudaFuncSetAttribute(gemm_kv_kernel,
                         cudaFuncAttributeMaxDynamicSharedMemorySize, GEMM_SMEM);
    cudaFuncSetAttribute(conv_off_kernel,
                         cudaFuncAttributeMaxDynamicSharedMemorySize, CONV_SMEM);

    dim3 ggrid(MTOT / 128, NC / 128);
    dim3 kvgrid(MTOT / 128, NC / 128, 2);
    dim3 agrid(NPIX / 128, HEADS, BB);

    // 1. q = x @ w_q + b_q   (3xTF32 compensated — R11 version)
    gemm_mma3_kernel<<<ggrid, 256, G3_SMEM>>>(x, w_q, b_q, pq);
    // 2. grouped 3x3 conv on q -> g_t
    conv_off_kernel<<<BB * 8 * GROUPS, 256, CONV_SMEM>>>(w_off0, b_off0);
    // 3. LN + GELU + offset proj + tanh + ref + bilinear sample (2 px/block)
    ln_sample_kernel<<<MTOT / 2, 768>>>(ln_g, ln_b, w_offp, x);
    // 4. fused k+v projections (tf32 cp.async — R11 config)
    gemm_kv_kernel<<<kvgrid, 256, GEMM_SMEM>>>(pxs, w_k, b_k, pk, w_v, b_v, pv);
    // 5. attention (fp16 m16n8k16 flash, register-resident P) -> g_o
    attn_mma_kernel<<<agrid, 256, ATTN_SMEM>>>();
    // 6. y = o @ w_o + b_o -> d_out (tf32 cp.async — R11 config)
    gemm_mma_kernel<<<ggrid, 256, GEMM_SMEM>>>(po, w_o, b_o, out);
}

// round 17
// speedup vs baseline: 1.0868x; 1.0118x over previous
#include <cuda_runtime.h>
#include <cuda_fp16.h>
#include <math.h>
#include <stdint.h>

// ---------------------------------------------------------------------------
// Problem constants
// ---------------------------------------------------------------------------
#define BB     8
#define HH     32
#define WW     32
#define NC     384
#define GROUPS 6
#define HEADS  12
#define HC     32
#define GC     64
#define NPIX   (HH*WW)          // 1024
#define MTOT   (BB*NPIX)        // 8192
#define NCH    12               // K chunks of 32

// ---------------------------------------------------------------------------
// Scratch (static device globals — no allocation allowed)
// ---------------------------------------------------------------------------
__device__ float g_q  [MTOT*NC];
__device__ float g_t  [MTOT*NC];
__device__ float g_xs [MTOT*NC];
__device__ float g_k  [MTOT*NC];
__device__ float g_v  [MTOT*NC];
__device__ float g_o  [MTOT*NC];

// ---------------------------------------------------------------------------
// mma.sync / packed-f32x2 / cp.async helpers (base sm_103 ISA)
// ---------------------------------------------------------------------------
__device__ __forceinline__ uint32_t f2tf32(float x) {
    uint32_t r;
    asm("cvt.rna.tf32.f32 %0, %1;" : "=r"(r) : "f"(x));
    return r;
}
__device__ __forceinline__ float ex2f(float x) {
    float r;
    asm("ex2.approx.f32 %0, %1;" : "=f"(r) : "f"(x));
    return r;
}
__device__ __forceinline__ uint32_t f16x2(float lo, float hi) {
    uint32_t r;
    asm("cvt.rn.f16x2.f32 %0, %1, %2;" : "=r"(r) : "f"(hi), "f"(lo));
    return r;
}
__device__ __forceinline__ uint16_t f16b(float x) {
    uint16_t r;
    asm("cvt.rn.f16.f32 %0, %1;" : "=h"(r) : "f"(x));
    return r;
}
__device__ __forceinline__ void mma_tf32(float* c, const uint32_t* a, const uint32_t* b) {
    asm volatile(
        "mma.sync.aligned.m16n8k8.row.col.f32.tf32.tf32.f32 "
        "{%0,%1,%2,%3}, {%4,%5,%6,%7}, {%8,%9}, {%0,%1,%2,%3};"
        : "+f"(c[0]), "+f"(c[1]), "+f"(c[2]), "+f"(c[3])
        : "r"(a[0]), "r"(a[1]), "r"(a[2]), "r"(a[3]), "r"(b[0]), "r"(b[1]));
}
__device__ __forceinline__ void mma_f16(float* c, const uint32_t* a, const uint32_t* b) {
    asm volatile(
        "mma.sync.aligned.m16n8k16.row.col.f32.f16.f16.f32 "
        "{%0,%1,%2,%3}, {%4,%5,%6,%7}, {%8,%9}, {%0,%1,%2,%3};"
        : "+f"(c[0]), "+f"(c[1]), "+f"(c[2]), "+f"(c[3])
        : "r"(a[0]), "r"(a[1]), "r"(a[2]), "r"(a[3]), "r"(b[0]), "r"(b[1]));
}
#define FMA2(d, a, b) \
    asm("fma.rn.f32x2 %0, %1, %2, %0;" : "+l"(d) : "l"(a), "l"(b))
__device__ __forceinline__ uint64_t packf2(float lo, float hi) {
    uint64_t r;
    asm("mov.b64 %0, {%1, %2};" : "=l"(r) : "f"(lo), "f"(hi));
    return r;
}
__device__ __forceinline__ float2 unpackf2(uint64_t v) {
    float2 r;
    asm("mov.b64 {%0, %1}, %2;" : "=f"(r.x), "=f"(r.y) : "l"(v));
    return r;
}
__device__ __forceinline__ void cp16(uint32_t saddr, const void* gptr) {
    asm volatile("cp.async.ca.shared.global [%0], [%1], 16;"
                 :: "r"(saddr), "l"(gptr));
}
#define CP_COMMIT() asm volatile("cp.async.commit_group;" ::: "memory")
#define CP_WAIT0()  asm volatile("cp.async.wait_group 0;"  ::: "memory")

// single dynamic-smem symbol for the whole TU
extern __shared__ uint32_t dynsm[];

// ---------------------------------------------------------------------------
// Pipelined tf32 mma GEMM (R11): 256 thr, warp tile 32x64, cp.async
// double-buffered raw fp32 tiles, cvt at fragment load.
// ---------------------------------------------------------------------------
#define GSA 36
#define GSB 136
#define GEMM_SMEM ((2*128*GSA + 2*32*GSB) * 4)

__device__ __forceinline__ void gemm_body_v3(
    const float* __restrict__ A, const float* __restrict__ W,
    const float* __restrict__ bias, float* __restrict__ C)
{
    float* As = reinterpret_cast<float*>(dynsm);
    float* Bs = As + 2 * 128 * GSA;
    const uint32_t sA = (uint32_t)__cvta_generic_to_shared(As);
    const uint32_t sB = (uint32_t)__cvta_generic_to_shared(Bs);

    const int tid = threadIdx.x, lane = tid & 31, wid = tid >> 5;
    const int wm = wid & 3, wn = wid >> 2;
    const int bm = blockIdx.x * 128, bn = blockIdx.y * 128;
    const int lq = lane >> 2, lr = lane & 3;

    float acc[2][8][4];
    #pragma unroll
    for (int i = 0; i < 2; i++)
        #pragma unroll
        for (int j = 0; j < 8; j++)
            #pragma unroll
            for (int t = 0; t < 4; t++) acc[i][j][t] = 0.f;

    auto stage = [&](int c, int buf) {
        #pragma unroll
        for (int l = 0; l < 4; l++) {
            int idx = tid + l * 256;
            int ra = idx >> 3, ca = idx & 7;
            cp16(sA + (buf * 128 * GSA + ra * GSA + ca * 4) * 4,
                 &A[(size_t)(bm + ra) * NC + c * 32 + ca * 4]);
            int rb = idx >> 5, cb = idx & 31;
            cp16(sB + (buf * 32 * GSB + rb * GSB + cb * 4) * 4,
                 &W[(size_t)(c * 32 + rb) * NC + bn + cb * 4]);
        }
        CP_COMMIT();
    };

    stage(0, 0);
    CP_WAIT0();
    __syncthreads();

    for (int c = 0; c < NCH; c++) {
        const int buf = c & 1;
        const bool more = (c + 1 < NCH);
        if (more) stage(c + 1, buf ^ 1);

        const float* Ab = As + buf * 128 * GSA;
        const float* Bb = Bs + buf * 32 * GSB;
        #pragma unroll
        for (int ks = 0; ks < 4; ks++) {
            const int k0 = ks * 8;
            uint32_t af[2][4];
            #pragma unroll
            for (int i = 0; i < 2; i++) {
                const int rb = wm * 32 + i * 16;
                af[i][0] = f2tf32(Ab[(rb +     lq) * GSA + k0 +     lr]);
                af[i][1] = f2tf32(Ab[(rb + 8 + lq) * GSA + k0 +     lr]);
                af[i][2] = f2tf32(Ab[(rb +     lq) * GSA + k0 + 4 + lr]);
                af[i][3] = f2tf32(Ab[(rb + 8 + lq) * GSA + k0 + 4 + lr]);
            }
            #pragma unroll
            for (int j = 0; j < 8; j++) {
                uint32_t bf[2];
                const int col = wn * 64 + j * 8 + lq;
                bf[0] = f2tf32(Bb[(k0 +     lr) * GSB + col]);
                bf[1] = f2tf32(Bb[(k0 + 4 + lr) * GSB + col]);
                mma_tf32(acc[0][j], af[0], bf);
                mma_tf32(acc[1][j], af[1], bf);
            }
        }
        if (more) CP_WAIT0();
        __syncthreads();
    }

    #pragma unroll
    for (int j = 0; j < 8; j++) {
        const int col = bn + wn * 64 + j * 8 + lr * 2;
        const float b0 = bias[col], b1 = bias[col + 1];
        #pragma unroll
        for (int i = 0; i < 2; i++) {
            const int r0 = bm + wm * 32 + i * 16 + lq;
            *reinterpret_cast<float2*>(&C[(size_t)r0 * NC + col]) =
                make_float2(acc[i][j][0] + b0, acc[i][j][1] + b1);
            *reinterpret_cast<float2*>(&C[(size_t)(r0 + 8) * NC + col]) =
                make_float2(acc[i][j][2] + b0, acc[i][j][3] + b1);
        }
    }
}

__global__ __launch_bounds__(256) void gemm_mma_kernel(
    const float* __restrict__ A, const float* __restrict__ W,
    const float* __restrict__ bias, float* __restrict__ C)
{
    gemm_body_v3(A, W, bias, C);
}

__global__ __launch_bounds__(256) void gemm_kv_kernel(
    const float* __restrict__ A,
    const float* __restrict__ Wk, const float* __restrict__ bk, float* __restrict__ K,
    const float* __restrict__ Wv, const float* __restrict__ bv, float* __restrict__ V)
{
    if (blockIdx.z == 0)
        gemm_body_v3(A, Wk, bk, K);
    else
        gemm_body_v3(A, Wv, bv, V);
}

// ---------------------------------------------------------------------------
// 3xTF32 compensated GEMM (near-fp32) — q projection only (R11 version).
// ---------------------------------------------------------------------------
#define G3_SMEM ((128*GSA*2 + 32*GSB*2) * 4)

__global__ __launch_bounds__(256) void gemm_mma3_kernel(
    const float* __restrict__ A, const float* __restrict__ W,
    const float* __restrict__ bias, float* __restrict__ C)
{
    uint32_t* s3 = dynsm;
    uint32_t* AsH = s3;
    uint32_t* AsL = s3 + 128 * GSA;
    uint32_t* BsH = s3 + 2 * 128 * GSA;
    uint32_t* BsL = BsH + 32 * GSB;

    const int tid = threadIdx.x, lane = tid & 31, wid = tid >> 5;
    const int wm = wid & 3, wn = wid >> 2;
    const int bm = blockIdx.x * 128, bn = blockIdx.y * 128;
    const int lq = lane >> 2, lr = lane & 3;

    float acc[2][8][4];
    #pragma unroll
    for (int i = 0; i < 2; i++)
        #pragma unroll
        for (int j = 0; j < 8; j++)
            #pragma unroll
            for (int t = 0; t < 4; t++) acc[i][j][t] = 0.f;

    for (int c = 0; c < NCH; c++) {
        #pragma unroll
        for (int l = 0; l < 4; l++) {
            int idx = tid + l * 256;
            int row = idx >> 3, c4 = idx & 7;
            float4 v = *reinterpret_cast<const float4*>(
                &A[(size_t)(bm + row) * NC + c * 32 + c4 * 4]);
            uint32_t* dh = &AsH[row * GSA + c4 * 4];
            uint32_t* dl = &AsL[row * GSA + c4 * 4];
            uint32_t h;
            h = f2tf32(v.x); dh[0] = h; dl[0] = f2tf32(v.x - __uint_as_float(h));
            h = f2tf32(v.y); dh[1] = h; dl[1] = f2tf32(v.y - __uint_as_float(h));
            h = f2tf32(v.z); dh[2] = h; dl[2] = f2tf32(v.z - __uint_as_float(h));
            h = f2tf32(v.w); dh[3] = h; dl[3] = f2tf32(v.w - __uint_as_float(h));
        }
        #pragma unroll
        for (int l = 0; l < 4; l++) {
            int idx = tid + l * 256;
            int row = idx >> 5, c4 = idx & 31;
            float4 v = *reinterpret_cast<const float4*>(
                &W[(size_t)(c * 32 + row) * NC + bn + c4 * 4]);
            uint32_t* dh = &BsH[row * GSB + c4 * 4];
            uint32_t* dl = &BsL[row * GSB + c4 * 4];
            uint32_t h;
            h = f2tf32(v.x); dh[0] = h; dl[0] = f2tf32(v.x - __uint_as_float(h));
            h = f2tf32(v.y); dh[1] = h; dl[1] = f2tf32(v.y - __uint_as_float(h));
            h = f2tf32(v.z); dh[2] = h; dl[2] = f2tf32(v.z - __uint_as_float(h));
            h = f2tf32(v.w); dh[3] = h; dl[3] = f2tf32(v.w - __uint_as_float(h));
        }
        __syncthreads();
        #pragma unroll
        for (int ks = 0; ks < 4; ks++) {
            const int k0 = ks * 8;
            uint32_t afh[2][4], afl[2][4];
            #pragma unroll
            for (int i = 0; i < 2; i++) {
                const int rb = wm * 32 + i * 16;
                afh[i][0] = AsH[(rb +     lq) * GSA + k0 +     lr];
                afh[i][1] = AsH[(rb + 8 + lq) * GSA + k0 +     lr];
                afh[i][2] = AsH[(rb +     lq) * GSA + k0 + 4 + lr];
                afh[i][3] = AsH[(rb + 8 + lq) * GSA + k0 + 4 + lr];
                afl[i][0] = AsL[(rb +     lq) * GSA + k0 +     lr];
                afl[i][1] = AsL[(rb + 8 + lq) * GSA + k0 +     lr];
                afl[i][2] = AsL[(rb +     lq) * GSA + k0 + 4 + lr];
                afl[i][3] = AsL[(rb + 8 + lq) * GSA + k0 + 4 + lr];
            }
            #pragma unroll
            for (int j = 0; j < 8; j++) {
                uint32_t bfh[2], bfl[2];
                const int col = wn * 64 + j * 8 + lq;
                bfh[0] = BsH[(k0 +     lr) * GSB + col];
                bfh[1] = BsH[(k0 + 4 + lr) * GSB + col];
                bfl[0] = BsL[(k0 +     lr) * GSB + col];
                bfl[1] = BsL[(k0 + 4 + lr) * GSB + col];
                #pragma unroll
                for (int i = 0; i < 2; i++) {
                    mma_tf32(acc[i][j], afl[i], bfh);
                    mma_tf32(acc[i][j], afh[i], bfl);
                    mma_tf32(acc[i][j], afh[i], bfh);
                }
            }
        }
        __syncthreads();
    }
    #pragma unroll
    for (int j = 0; j < 8; j++) {
        const int col = bn + wn * 64 + j * 8 + lr * 2;
        const float b0 = bias[col], b1 = bias[col + 1];
        #pragma unroll
        for (int i = 0; i < 2; i++) {
            const int r0 = bm + wm * 32 + i * 16 + lq;
            *reinterpret_cast<float2*>(&C[(size_t)r0 * NC + col]) =
                make_float2(acc[i][j][0] + b0, acc[i][j][1] + b1);
            *reinterpret_cast<float2*>(&C[(size_t)(r0 + 8) * NC + col]) =
                make_float2(acc[i][j][2] + b0, acc[i][j][3] + b1);
        }
    }
}

// ---------------------------------------------------------------------------
// Flash attention v4 (R11): fp16 m16n8k16, fixed-max softmax,
// register-resident P, double-buffered fp16 K/V via register prefetch.
// ---------------------------------------------------------------------------
#define KW  20
#define VTW 36
#define ATTN_SMEM (2*64*KW*4 + 2*32*VTW*4)

__global__ __launch_bounds__(256) void attn_mma_kernel()
{
    uint32_t* Khw = dynsm;
    uint32_t* Vtw = dynsm + 2 * 64 * KW;

    const int tid = threadIdx.x, lane = tid & 31, wid = tid >> 5;
    const int lq = lane >> 2, lr = lane & 3;
    const int qt = blockIdx.x, h = blockIdx.y, b = blockIdx.z;
    const int q0 = qt * 128;

    const float qscale = 0.17677669529663689f * 1.4426950408889634f;
    uint32_t* Qw = dynsm;
    #pragma unroll
    for (int l = 0; l < 4; l++) {
        int idx = tid + l * 256;
        int row = idx >> 3, c4 = idx & 7;
        float4 v = *reinterpret_cast<const float4*>(
            &g_q[((size_t)b * NPIX + q0 + row) * NC + h * HC + c4 * 4]);
        Qw[row * KW + c4 * 2 + 0] = f16x2(v.x * qscale, v.y * qscale);
        Qw[row * KW + c4 * 2 + 1] = f16x2(v.z * qscale, v.w * qscale);
    }
    __syncthreads();
    uint32_t qf[2][4];
    {
        const int rb = wid * 16;
        #pragma unroll
        for (int ks = 0; ks < 2; ks++) {
            qf[ks][0] = Qw[(rb +     lq) * KW + lr +     8 * ks];
            qf[ks][1] = Qw[(rb + 8 + lq) * KW + lr +     8 * ks];
            qf[ks][2] = Qw[(rb +     lq) * KW + lr + 4 + 8 * ks];
            qf[ks][3] = Qw[(rb + 8 + lq) * KW + lr + 4 + 8 * ks];
        }
    }
    __syncthreads();

    float o[4][4];
    #pragma unroll
    for (int j = 0; j < 4; j++)
        #pragma unroll
        for (int t = 0; t < 4; t++) o[j][t] = 0.f;
    float l0 = 0.f, l1 = 0.f;

    auto ldtile = [&](int kt, float4* rk, float4* rv) {
        #pragma unroll
        for (int l = 0; l < 2; l++) {
            int idx = tid + l * 256;
            int key = idx >> 3, c4 = idx & 7;
            size_t base = ((size_t)b * NPIX + kt + key) * NC + h * HC + c4 * 4;
            rk[l] = *reinterpret_cast<const float4*>(&g_k[base]);
            rv[l] = *reinterpret_cast<const float4*>(&g_v[base]);
        }
    };
    auto sttile = [&](int buf, const float4* rk, const float4* rv) {
        uint32_t* K = Khw + buf * 64 * KW;
        uint16_t* Vt = reinterpret_cast<uint16_t*>(Vtw + buf * 32 * VTW);
        #pragma unroll
        for (int l = 0; l < 2; l++) {
            int idx = tid + l * 256;
            int key = idx >> 3, c4 = idx & 7;
            K[key * KW + c4 * 2 + 0] = f16x2(rk[l].x, rk[l].y);
            K[key * KW + c4 * 2 + 1] = f16x2(rk[l].z, rk[l].w);
            Vt[(c4 * 4 + 0) * (2 * VTW) + key] = f16b(rv[l].x);
            Vt[(c4 * 4 + 1) * (2 * VTW) + key] = f16b(rv[l].y);
            Vt[(c4 * 4 + 2) * (2 * VTW) + key] = f16b(rv[l].z);
            Vt[(c4 * 4 + 3) * (2 * VTW) + key] = f16b(rv[l].w);
        }
    };

    {
        float4 rk[2], rv[2];
        ldtile(0, rk, rv);
        sttile(0, rk, rv);
    }
    __syncthreads();

    for (int it = 0; it < 16; it++) {
        const int buf = it & 1;
        const bool more = (it < 15);
        float4 rk[2], rv[2];
        if (more) ldtile((it + 1) * 64, rk, rv);

        const uint32_t* K = Khw + buf * 64 * KW;
        const uint32_t* V = Vtw + buf * 32 * VTW;

        float s[8][4];
        #pragma unroll
        for (int j = 0; j < 8; j++)
            #pragma unroll
            for (int t = 0; t < 4; t++) s[j][t] = 0.f;
        #pragma unroll
        for (int ks = 0; ks < 2; ks++) {
            #pragma unroll
            for (int j = 0; j < 8; j++) {
                uint32_t bf[2];
                const int col = j * 8 + lq;
                bf[0] = K[col * KW + lr +     8 * ks];
                bf[1] = K[col * KW + lr + 4 + 8 * ks];
                mma_f16(s[j], qf[ks], bf);
            }
        }

        #pragma unroll
        for (int j = 0; j < 8; j++) {
            s[j][0] = ex2f(s[j][0]);
            s[j][1] = ex2f(s[j][1]);
            s[j][2] = ex2f(s[j][2]);
            s[j][3] = ex2f(s[j][3]);
            l0 += s[j][0] + s[j][1];
            l1 += s[j][2] + s[j][3];
        }

        if (more) sttile(buf ^ 1, rk, rv);

        #pragma unroll
        for (int ks = 0; ks < 4; ks++) {
            uint32_t ap[4];
            ap[0] = f16x2(s[2*ks    ][0], s[2*ks    ][1]);
            ap[1] = f16x2(s[2*ks    ][2], s[2*ks    ][3]);
            ap[2] = f16x2(s[2*ks + 1][0], s[2*ks + 1][1]);
            ap[3] = f16x2(s[2*ks + 1][2], s[2*ks + 1][3]);
            #pragma unroll
            for (int j = 0; j < 4; j++) {
                uint32_t bf[2];
                const int n = j * 8 + lq;
                bf[0] = V[n * VTW + lr +     8 * ks];
                bf[1] = V[n * VTW + lr + 4 + 8 * ks];
                mma_f16(o[j], ap, bf);
            }
        }
        __syncthreads();
    }

    l0 += __shfl_xor_sync(0xffffffffu, l0, 1);
    l0 += __shfl_xor_sync(0xffffffffu, l0, 2);
    l1 += __shfl_xor_sync(0xffffffffu, l1, 1);
    l1 += __shfl_xor_sync(0xffffffffu, l1, 2);
    const float il0 = 1.f / l0, il1 = 1.f / l1;
    const int rg = q0 + wid * 16 + lq;
    #pragma unroll
    for (int j = 0; j < 4; j++) {
        const int col = h * HC + j * 8 + lr * 2;
        *reinterpret_cast<float2*>(&g_o[((size_t)b * NPIX + rg) * NC + col]) =
            make_float2(o[j][0] * il0, o[j][1] * il0);
        *reinterpret_cast<float2*>(&g_o[((size_t)b * NPIX + rg + 8) * NC + col]) =
            make_float2(o[j][2] * il1, o[j][3] * il1);
    }
}

// ---------------------------------------------------------------------------
// Grouped 3x3 conv (packed fma.rn.f32x2, bit-exact fp32) — R11 version.
// ---------------------------------------------------------------------------
#define CONV_SMEM (64 * 6 * 36 * 4)

__global__ __launch_bounds__(256) void conv_off_kernel(
    const float* __restrict__ W, const float* __restrict__ bias)
{
    float* qs = reinterpret_cast<float*>(dynsm);
    const int bid = blockIdx.x;
    const int g  = bid % GROUPS;
    const int yt = (bid / GROUPS) & 7;
    const int b  = bid / (GROUPS * 8);
    const int y0 = yt * 4;
    const int tid = threadIdx.x;

    for (int i = tid; i < 64 * 6 * 34; i += 256) {
        int c  = i & 63;
        int xx = (i >> 6) % 34;
        int r  = i / (64 * 34);
        int yy = y0 + r - 1;
        float v = 0.f;
        if (xx >= 1 && xx <= 32 && yy >= 0 && yy < HH)
            v = g_q[((size_t)(b*HH + yy)*WW + (xx-1)) * NC + g*GC + c];
        qs[(c * 6 + r) * 36 + xx] = v;
    }
    __syncthreads();

    const int ty = tid >> 6;
    const int x0 = ((tid >> 4) & 3) * 8;
    const int oc = (tid & 15) * 4;
    const int y  = y0 + ty;

    uint64_t acc01[8], acc23[8];
    {
        float4 bv = *reinterpret_cast<const float4*>(&bias[g*GC + oc]);
        uint64_t b01 = packf2(bv.x, bv.y), b23 = packf2(bv.z, bv.w);
        #pragma unroll
        for (int xi = 0; xi < 8; xi++) { acc01[xi] = b01; acc23[xi] = b23; }
    }

    #pragma unroll
    for (int dy = 0; dy < 3; dy++) {
        const int r = ty + dy;
        #pragma unroll 2
        for (int ic = 0; ic < GC; ic++) {
            const float* qrow = &qs[(ic * 6 + r) * 36 + x0];
            uint64_t qp[10];
            #pragma unroll
            for (int j = 0; j < 10; j++) {
                float qv = qrow[j];
                qp[j] = packf2(qv, qv);
            }
            const uint64_t* wp0 = reinterpret_cast<const uint64_t*>(
                &W[(size_t)((dy*3 + 0) * GC + ic) * NC + g*GC + oc]);
            const uint64_t* wp1 = reinterpret_cast<const uint64_t*>(
                &W[(size_t)((dy*3 + 1) * GC + ic) * NC + g*GC + oc]);
            const uint64_t* wp2 = reinterpret_cast<const uint64_t*>(
                &W[(size_t)((dy*3 + 2) * GC + ic) * NC + g*GC + oc]);
            const uint64_t w0a = wp0[0], w0b = wp0[1];
            const uint64_t w1a = wp1[0], w1b = wp1[1];
            const uint64_t w2a = wp2[0], w2b = wp2[1];
            #pragma unroll
            for (int xi = 0; xi < 8; xi++) {
                FMA2(acc01[xi], w0a, qp[xi]);
                FMA2(acc23[xi], w0b, qp[xi]);
                FMA2(acc01[xi], w1a, qp[xi + 1]);
                FMA2(acc23[xi], w1b, qp[xi + 1]);
                FMA2(acc01[xi], w2a, qp[xi + 2]);
                FMA2(acc23[xi], w2b, qp[xi + 2]);
            }
        }
    }

    #pragma unroll
    for (int xi = 0; xi < 8; xi++) {
        float2 a = unpackf2(acc01[xi]);
        float2 c = unpackf2(acc23[xi]);
        float4 o = make_float4(a.x, a.y, c.x, c.y);
        *reinterpret_cast<float4*>(
            &g_t[((size_t)(b*HH + y)*WW + x0 + xi) * NC + g*GC + oc]) = o;
    }
}

// ---------------------------------------------------------------------------
// Fused LN + erf-GELU + offset proj + tanh*range + ref grid + sample (R11:
// one pixel per block, 384 threads).
// ---------------------------------------------------------------------------
__global__ __launch_bounds__(384) void ln_sample_kernel(
    const float* __restrict__ ln_g, const float* __restrict__ ln_b,
    const float* __restrict__ wp, const float* __restrict__ x)
{
    const int p   = blockIdx.x;
    const int tid = threadIdx.x;
    const int wid  = tid >> 5;
    const int lane = tid & 31;

    float v = g_t[(size_t)p * NC + tid];

    __shared__ float red[2][12];
    __shared__ float sv[NC];
    __shared__ float spos[12];

    float s = v, sq = v * v;
    #pragma unroll
    for (int o = 16; o > 0; o >>= 1) {
        s  += __shfl_xor_sync(0xffffffffu, s,  o);
        sq += __shfl_xor_sync(0xffffffffu, sq, o);
    }
    if (lane == 0) { red[0][wid] = s; red[1][wid] = sq; }
    __syncthreads();
    if (tid < 32) {
        float a = (tid < 12) ? red[0][tid] : 0.f;
        float c = (tid < 12) ? red[1][tid] : 0.f;
        #pragma unroll
        for (int o = 8; o > 0; o >>= 1) {
            a += __shfl_xor_sync(0xffffffffu, a, o);
            c += __shfl_xor_sync(0xffffffffu, c, o);
        }
        if (tid == 0) { red[0][0] = a; red[1][0] = c; }
    }
    __syncthreads();
    const float mu  = red[0][0] * (1.f / NC);
    const float var = red[1][0] * (1.f / NC) - mu * mu;
    float nv = (v - mu) * rsqrtf(var + 1e-3f) * ln_g[tid] + ln_b[tid];
    nv = 0.5f * nv * (1.f + erff(nv * 0.70710678118654752f));

    sv[tid] = nv;
    __syncthreads();

    const int grp = wid >> 1, comp = wid & 1;
    float part = sv[grp*GC + lane]      * wp[lane * 2 + comp]
               + sv[grp*GC + 32 + lane] * wp[(32 + lane) * 2 + comp];
    #pragma unroll
    for (int o = 16; o > 0; o >>= 1)
        part += __shfl_xor_sync(0xffffffffu, part, o);

    const int pix = p & 1023;
    if (lane == 0) {
        const int yy = pix >> 5, xx = pix & 31;
        float refv = (comp == 0) ? (float)xx : (float)yy;
        spos[grp*2 + comp] = tanhf(part) * 16.f + refv;
    }
    __syncthreads();

    const int b = p >> 10;
    const int g = tid >> 6, c = tid & 63;
    const float p0 = spos[g*2 + 0];
    const float p1 = spos[g*2 + 1];
    const float xqf = p1 + 1.f;
    const float yqf = p0 + 1.f;
    const float x0f = fminf(fmaxf(floorf(xqf), 0.f), 32.f);
    const float y0f = fminf(fmaxf(floorf(yqf), 0.f), 32.f);
    const float ax = fminf(fmaxf(xqf - x0f, 0.f), 1.f);
    const float ay = fminf(fmaxf(yqf - y0f, 0.f), 1.f);
    const int x0 = (int)x0f, y0 = (int)y0f;

    const size_t choff = (size_t)g * GC + c;
    auto fetch = [&](int yy2, int xx2) -> float {
        if (yy2 < 1 || yy2 > 32 || xx2 < 1 || xx2 > 32) return 0.f;
        return x[((size_t)(b*HH + (yy2-1)) * WW + (xx2-1)) * NC + choff];
    };
    float tl = fetch(y0,     x0);
    float tr = fetch(y0,     x0 + 1);
    float bl = fetch(y0 + 1, x0);
    float br = fetch(y0 + 1, x0 + 1);
    float top = tl + ax * (tr - tl);
    float bot = bl + ax * (br - bl);
    g_xs[((size_t)b * NPIX + pix) * NC + choff] = top + ay * (bot - top);
}

// ---------------------------------------------------------------------------
// Launch
// ---------------------------------------------------------------------------
extern "C" void kernel_launch(void* const* d_in, const int* in_sizes, int n_in,
                              void* d_out, int out_size)
{
    const float* x      = (const float*)d_in[0];
    const float* w_q    = (const float*)d_in[1];
    const float* b_q    = (const float*)d_in[2];
    const float* w_off0 = (const float*)d_in[3];
    const float* b_off0 = (const float*)d_in[4];
    const float* ln_g   = (const float*)d_in[5];
    const float* ln_b   = (const float*)d_in[6];
    const float* w_offp = (const float*)d_in[7];
    const float* w_k    = (const float*)d_in[8];
    const float* b_k    = (const float*)d_in[9];
    const float* w_v    = (const float*)d_in[10];
    const float* b_v    = (const float*)d_in[11];
    const float* w_o    = (const float*)d_in[12];
    const float* b_o    = (const float*)d_in[13];
    float* out = (float*)d_out;

    float *pq, *pxs, *pk, *pv, *po;
    cudaGetSymbolAddress((void**)&pq,  g_q);
    cudaGetSymbolAddress((void**)&pxs, g_xs);
    cudaGetSymbolAddress((void**)&pk,  g_k);
    cudaGetSymbolAddress((void**)&pv,  g_v);
    cudaGetSymbolAddress((void**)&po,  g_o);

    cudaFuncSetAttribute(attn_mma_kernel,
                         cudaFuncAttributeMaxDynamicSharedMemorySize, ATTN_SMEM);
    cudaFuncSetAttribute(gemm_mma3_kernel,
                         cudaFuncAttributeMaxDynamicSharedMemorySize, G3_SMEM);
    cudaFuncSetAttribute(gemm_mma_kernel,
                         cudaFuncAttributeMaxDynamicSharedMemorySize, GEMM_SMEM);
    cudaFuncSetAttribute(gemm_kv_kernel,
                         cudaFuncAttributeMaxDynamicSharedMemorySize, GEMM_SMEM);
    cudaFuncSetAttribute(conv_off_kernel,
                         cudaFuncAttributeMaxDynamicSharedMemorySize, CONV_SMEM);

    dim3 ggrid(MTOT / 128, NC / 128);
    dim3 kvgrid(MTOT / 128, NC / 128, 2);
    dim3 agrid(NPIX / 128, HEADS, BB);

    // 1. q = x @ w_q + b_q   (3xTF32 compensated)
    gemm_mma3_kernel<<<ggrid, 256, G3_SMEM>>>(x, w_q, b_q, pq);
    // 2. grouped 3x3 conv on q -> g_t
    conv_off_kernel<<<BB * 8 * GROUPS, 256, CONV_SMEM>>>(w_off0, b_off0);
    // 3. LN + GELU + offset proj + tanh + ref + bilinear sample -> g_xs
    ln_sample_kernel<<<MTOT, NC>>>(ln_g, ln_b, w_offp, x);
    // 4. fused k+v projections (tf32 cp.async)
    gemm_kv_kernel<<<kvgrid, 256, GEMM_SMEM>>>(pxs, w_k, b_k, pk, w_v, b_v, pv);
    // 5. attention (fp16 m16n8k16 flash, register-resident P) -> g_o
    attn_mma_kernel<<<agrid, 256, ATTN_SMEM>>>();
    // 6. y = o @ w_o + b_o -> d_out (tf32 cp.async)
    gemm_mma_kernel<<<ggrid, 256, GEMM_SMEM>>>(po, w_o, b_o, out);
}